// round 1
// baseline (speedup 1.0000x reference)
#include <cuda_runtime.h>

// Problem dims (fixed by the dataset)
#define BB 8
#define NSEQ 2048
#define DD 1024
#define DKK 64
#define MTOT (BB*NSEQ)   // 16384

// ---------------- scratch (static __device__ — no allocation) ----------------
__device__ float g_Wcat[192*DD];          // [Wq;Wk;W1] stacked, 192x1024
__device__ float g_QKF[MTOT*192];         // per row: Q[0:64] K[64:128] F[128:192]
__device__ float g_Apart[4*BB*DKK*DD];    // split-L partials of A
__device__ float g_A[BB*DKK*DD];          // A_b = K_b^T x_b
__device__ float g_U2[DKK*DD];            // U2 = W1 @ Wv
__device__ float g_T[BB*DKK*DKK];         // T_b = A_b @ U2^T
__device__ float g_fc[MTOT*DKK];          // fc = F + Q @ T

// ============================================================================
// C[M,N] = A[M,K] * B[N,K]^T   (+ optional Cadd), batched via blockIdx.z
// ============================================================================
template<int BM,int BN,int BK,int TM,int TN,bool ADD>
__global__ void __launch_bounds__((BM/TM)*(BN/TN))
gemm_abt(const float* __restrict__ A, long sA, int lda,
         const float* __restrict__ B, long sB, int ldb,
         const float* __restrict__ Cadd, long sAdd, int ldadd,
         float* __restrict__ C, long sC, int ldc,
         int K)
{
    constexpr int THREADS = (BM/TM)*(BN/TN);
    __shared__ float As[BK][BM];
    __shared__ float Bs[BK][BN];

    const int bz = blockIdx.z;
    A += bz * sA;  B += bz * sB;  C += bz * sC;
    const float* Cad = ADD ? (Cadd + bz * sAdd) : nullptr;

    const int m0 = blockIdx.y * BM;
    const int n0 = blockIdx.x * BN;
    const int tid = threadIdx.x;
    const int tx = tid % (BN/TN);
    const int ty = tid / (BN/TN);

    float acc[TM][TN];
    #pragma unroll
    for (int i = 0; i < TM; i++)
        #pragma unroll
        for (int j = 0; j < TN; j++) acc[i][j] = 0.f;

    for (int k0 = 0; k0 < K; k0 += BK) {
        // A tile: BM x BK, stored transposed As[k][m]
        #pragma unroll
        for (int e = 0; e < (BM*BK/4)/THREADS; e++) {
            int idx = tid + e*THREADS;
            int row = idx / (BK/4), cv = idx % (BK/4);
            float4 v = *(const float4*)(A + (long)(m0+row)*lda + k0 + cv*4);
            As[cv*4+0][row] = v.x;  As[cv*4+1][row] = v.y;
            As[cv*4+2][row] = v.z;  As[cv*4+3][row] = v.w;
        }
        // B tile: BN x BK, stored transposed Bs[k][n]
        #pragma unroll
        for (int e = 0; e < (BN*BK/4)/THREADS; e++) {
            int idx = tid + e*THREADS;
            int row = idx / (BK/4), cv = idx % (BK/4);
            float4 v = *(const float4*)(B + (long)(n0+row)*ldb + k0 + cv*4);
            Bs[cv*4+0][row] = v.x;  Bs[cv*4+1][row] = v.y;
            Bs[cv*4+2][row] = v.z;  Bs[cv*4+3][row] = v.w;
        }
        __syncthreads();
        #pragma unroll
        for (int k = 0; k < BK; k++) {
            float a[TM], b[TN];
            #pragma unroll
            for (int i = 0; i < TM; i += 4) *(float4*)(a+i) = *(const float4*)&As[k][ty*TM+i];
            #pragma unroll
            for (int j = 0; j < TN; j += 4) *(float4*)(b+j) = *(const float4*)&Bs[k][tx*TN+j];
            #pragma unroll
            for (int i = 0; i < TM; i++)
                #pragma unroll
                for (int j = 0; j < TN; j++) acc[i][j] += a[i]*b[j];
        }
        __syncthreads();
    }
    #pragma unroll
    for (int i = 0; i < TM; i++) {
        int row = m0 + ty*TM + i;
        #pragma unroll
        for (int j = 0; j < TN; j += 4) {
            float4 v;
            v.x = acc[i][j];   v.y = acc[i][j+1];
            v.z = acc[i][j+2]; v.w = acc[i][j+3];
            if (ADD) {
                float4 c = *(const float4*)(Cad + (long)row*ldadd + n0 + tx*TN + j);
                v.x += c.x; v.y += c.y; v.z += c.z; v.w += c.w;
            }
            *(float4*)(C + (long)row*ldc + n0 + tx*TN + j) = v;
        }
    }
}

// ============================================================================
// C[M,N] = A[M,K] * B[K,N]   (+ optional Cadd), batched via blockIdx.z
// ============================================================================
template<int BM,int BN,int BK,int TM,int TN,bool ADD>
__global__ void __launch_bounds__((BM/TM)*(BN/TN))
gemm_nn(const float* __restrict__ A, long sA, int lda,
        const float* __restrict__ B, long sB, int ldb,
        const float* __restrict__ Cadd, long sAdd, int ldadd,
        float* __restrict__ C, long sC, int ldc,
        int K)
{
    constexpr int THREADS = (BM/TM)*(BN/TN);
    __shared__ float As[BK][BM];
    __shared__ float Bs[BK][BN];

    const int bz = blockIdx.z;
    A += bz * sA;  B += bz * sB;  C += bz * sC;
    const float* Cad = ADD ? (Cadd + bz * sAdd) : nullptr;

    const int m0 = blockIdx.y * BM;
    const int n0 = blockIdx.x * BN;
    const int tid = threadIdx.x;
    const int tx = tid % (BN/TN);
    const int ty = tid / (BN/TN);

    float acc[TM][TN];
    #pragma unroll
    for (int i = 0; i < TM; i++)
        #pragma unroll
        for (int j = 0; j < TN; j++) acc[i][j] = 0.f;

    for (int k0 = 0; k0 < K; k0 += BK) {
        #pragma unroll
        for (int e = 0; e < (BM*BK/4)/THREADS; e++) {
            int idx = tid + e*THREADS;
            int row = idx / (BK/4), cv = idx % (BK/4);
            float4 v = *(const float4*)(A + (long)(m0+row)*lda + k0 + cv*4);
            As[cv*4+0][row] = v.x;  As[cv*4+1][row] = v.y;
            As[cv*4+2][row] = v.z;  As[cv*4+3][row] = v.w;
        }
        // B tile: BK x BN row-major, direct copy
        #pragma unroll
        for (int e = 0; e < (BK*BN/4)/THREADS; e++) {
            int idx = tid + e*THREADS;
            int row = idx / (BN/4), cv = idx % (BN/4);
            *(float4*)&Bs[row][cv*4] =
                *(const float4*)(B + (long)(k0+row)*ldb + n0 + cv*4);
        }
        __syncthreads();
        #pragma unroll
        for (int k = 0; k < BK; k++) {
            float a[TM], b[TN];
            #pragma unroll
            for (int i = 0; i < TM; i += 4) *(float4*)(a+i) = *(const float4*)&As[k][ty*TM+i];
            #pragma unroll
            for (int j = 0; j < TN; j += 4) *(float4*)(b+j) = *(const float4*)&Bs[k][tx*TN+j];
            #pragma unroll
            for (int i = 0; i < TM; i++)
                #pragma unroll
                for (int j = 0; j < TN; j++) acc[i][j] += a[i]*b[j];
        }
        __syncthreads();
    }
    #pragma unroll
    for (int i = 0; i < TM; i++) {
        int row = m0 + ty*TM + i;
        #pragma unroll
        for (int j = 0; j < TN; j += 4) {
            float4 v;
            v.x = acc[i][j];   v.y = acc[i][j+1];
            v.z = acc[i][j+2]; v.w = acc[i][j+3];
            if (ADD) {
                float4 c = *(const float4*)(Cad + (long)row*ldadd + n0 + tx*TN + j);
                v.x += c.x; v.y += c.y; v.z += c.z; v.w += c.w;
            }
            *(float4*)(C + (long)row*ldc + n0 + tx*TN + j) = v;
        }
    }
}

// ============================================================================
// C[BM,N] = A[L,BM]^T * B[L,N]  — reduction over rows L (split via blockIdx.y)
// ============================================================================
template<int BM,int BN,int BL,int TM,int TN>
__global__ void __launch_bounds__((BM/TM)*(BN/TN))
gemm_atb(const float* __restrict__ A, long sA, int lda,
         const float* __restrict__ B, long sB, int ldb,
         float* __restrict__ C, long sCb, long sSplit, int ldc,
         int Lchunk)
{
    constexpr int THREADS = (BM/TM)*(BN/TN);
    __shared__ float As[BL][BM];
    __shared__ float Bs[BL][BN];

    const int bz = blockIdx.z;
    const int sp = blockIdx.y;
    const long l0base = (long)sp * Lchunk;
    A += bz * sA;  B += bz * sB;
    C += bz * sCb + (long)sp * sSplit;

    const int n0 = blockIdx.x * BN;
    const int tid = threadIdx.x;
    const int tx = tid % (BN/TN);
    const int ty = tid / (BN/TN);

    float acc[TM][TN];
    #pragma unroll
    for (int i = 0; i < TM; i++)
        #pragma unroll
        for (int j = 0; j < TN; j++) acc[i][j] = 0.f;

    for (int l0 = 0; l0 < Lchunk; l0 += BL) {
        #pragma unroll
        for (int e = 0; e < (BM*BL/4)/THREADS; e++) {
            int idx = tid + e*THREADS;
            int row = idx / (BM/4), cv = idx % (BM/4);
            *(float4*)&As[row][cv*4] =
                *(const float4*)(A + (l0base + l0 + row)*lda + cv*4);
        }
        #pragma unroll
        for (int e = 0; e < (BN*BL/4)/THREADS; e++) {
            int idx = tid + e*THREADS;
            int row = idx / (BN/4), cv = idx % (BN/4);
            *(float4*)&Bs[row][cv*4] =
                *(const float4*)(B + (l0base + l0 + row)*ldb + n0 + cv*4);
        }
        __syncthreads();
        #pragma unroll
        for (int l = 0; l < BL; l++) {
            float a[TM], b[TN];
            #pragma unroll
            for (int i = 0; i < TM; i += 4) *(float4*)(a+i) = *(const float4*)&As[l][ty*TM+i];
            #pragma unroll
            for (int j = 0; j < TN; j += 4) *(float4*)(b+j) = *(const float4*)&Bs[l][tx*TN+j];
            #pragma unroll
            for (int i = 0; i < TM; i++)
                #pragma unroll
                for (int j = 0; j < TN; j++) acc[i][j] += a[i]*b[j];
        }
        __syncthreads();
    }
    #pragma unroll
    for (int i = 0; i < TM; i++) {
        int row = ty*TM + i;
        #pragma unroll
        for (int j = 0; j < TN; j += 4) {
            float4 v;
            v.x = acc[i][j];   v.y = acc[i][j+1];
            v.z = acc[i][j+2]; v.w = acc[i][j+3];
            *(float4*)(C + (long)row*ldc + n0 + tx*TN + j) = v;
        }
    }
}

// Sum the 4 split-L partials of A
__global__ void reduce4(const float* __restrict__ p, float* __restrict__ o, int n)
{
    int i = blockIdx.x * 256 + threadIdx.x;
    if (i < n) o[i] = (p[i] + p[i + n]) + (p[i + 2*n] + p[i + 3*n]);
}

// ============================================================================
extern "C" void kernel_launch(void* const* d_in, const int* in_sizes, int n_in,
                              void* d_out, int out_size)
{
    const float* x  = (const float*)d_in[0];   // [8,2048,1024]
    const float* Wq = (const float*)d_in[1];   // [64,1024]
    const float* Wk = (const float*)d_in[2];   // [64,1024]
    const float* Wv = (const float*)d_in[3];   // [1024,1024]
    const float* W1 = (const float*)d_in[4];   // [64,1024]
    const float* W2 = (const float*)d_in[5];   // [1024,64]
    float* out = (float*)d_out;                // [8,2048,1024]

    float *wcat, *qkf, *apart, *ga, *u2, *gt, *gfc;
    cudaGetSymbolAddress((void**)&wcat,  g_Wcat);
    cudaGetSymbolAddress((void**)&qkf,   g_QKF);
    cudaGetSymbolAddress((void**)&apart, g_Apart);
    cudaGetSymbolAddress((void**)&ga,    g_A);
    cudaGetSymbolAddress((void**)&u2,    g_U2);
    cudaGetSymbolAddress((void**)&gt,    g_T);
    cudaGetSymbolAddress((void**)&gfc,   g_fc);

    // Stack [Wq; Wk; W1] -> g_Wcat (D2D async, graph-capturable)
    cudaMemcpyAsync(wcat,            Wq, (size_t)DKK*DD*sizeof(float), cudaMemcpyDeviceToDevice);
    cudaMemcpyAsync(wcat + DKK*DD,   Wk, (size_t)DKK*DD*sizeof(float), cudaMemcpyDeviceToDevice);
    cudaMemcpyAsync(wcat + 2*DKK*DD, W1, (size_t)DKK*DD*sizeof(float), cudaMemcpyDeviceToDevice);

    // 1) QKF = x @ Wcat^T : [16384,192]
    gemm_abt<128,64,16,8,4,false><<<dim3(3,128,1),256>>>(
        x, 0, DD,  wcat, 0, DD,  nullptr, 0, 0,  qkf, 0, 192,  DD);

    // 2) A_b = K_b^T x_b : [8,64,1024], split L=2048 into 4 chunks of 512
    gemm_atb<64,64,32,4,4><<<dim3(16,4,8),256>>>(
        qkf + 64, (long)NSEQ*192, 192,
        x,        (long)NSEQ*DD,  DD,
        apart,    (long)DKK*DD, (long)BB*DKK*DD, DD,
        NSEQ/4);
    reduce4<<<(BB*DKK*DD + 255)/256, 256>>>(apart, ga, BB*DKK*DD);

    // 3) U2 = W1 @ Wv : [64,1024]
    gemm_nn<64,64,16,4,4,false><<<dim3(16,1,1),256>>>(
        W1, 0, DD,  Wv, 0, DD,  nullptr, 0, 0,  u2, 0, DD,  DD);

    // 4) T_b = A_b @ U2^T : [8,64,64]
    gemm_abt<64,64,16,4,4,false><<<dim3(1,1,8),256>>>(
        ga, (long)DKK*DD, DD,  u2, 0, DD,  nullptr, 0, 0,
        gt, (long)DKK*DKK, DKK,  DD);

    // 5) fc_b = F_b + Q_b @ T_b : [8,2048,64]
    gemm_nn<64,64,16,4,4,true><<<dim3(1,32,8),256>>>(
        qkf,       (long)NSEQ*192, 192,
        gt,        (long)DKK*DKK,  DKK,
        qkf + 128, (long)NSEQ*192, 192,
        gfc,       (long)NSEQ*DKK, DKK,
        DKK);

    // 6) out = fc @ W2^T : [16384,1024]
    gemm_abt<128,64,16,8,4,false><<<dim3(16,128,1),256>>>(
        gfc, 0, DKK,  W2, 0, DKK,  nullptr, 0, 0,  out, 0, DD,  DKK);
}

// round 2
// speedup vs baseline: 1.0798x; 1.0798x over previous
#include <cuda_runtime.h>
#include <cstdint>

// Problem dims (fixed by the dataset)
#define BB 8
#define NSEQ 2048
#define DD 1024
#define DKK 64
#define MTOT (BB*NSEQ)   // 16384

// ---------------- scratch (static __device__ — no allocation) ----------------
__device__ float g_Wcat[192*DD];          // [Wq;Wk;W1] stacked, 192x1024
__device__ float g_QKF[MTOT*192];         // per row: Q[0:64] K[64:128] F[128:192]
__device__ float g_Apart[4*BB*DKK*DD];    // split-L partials of A
__device__ float g_A[BB*DKK*DD];          // A_b = K_b^T x_b
__device__ float g_U2part[8*DKK*DD];      // split-K partials of U2
__device__ float g_U2[DKK*DD];            // U2 = W1 @ Wv
__device__ float g_T[BB*DKK*DKK];         // T_b = A_b @ U2^T
__device__ float g_fc[MTOT*DKK];          // fc = F + Q @ T

// ---------------------------------------------------------------------------
// tf32 helpers
// ---------------------------------------------------------------------------
__device__ __forceinline__ float tf32_rna(float x) {
    uint32_t r;
    asm("cvt.rna.tf32.f32 %0, %1;" : "=r"(r) : "f"(x));
    return __uint_as_float(r);   // fp32 bit pattern with low mantissa zeroed
}
__device__ __forceinline__ uint32_t f2u(float f) { return __float_as_uint(f); }

__device__ __forceinline__ void mma_tf32(float (&d)[4],
    uint32_t a0, uint32_t a1, uint32_t a2, uint32_t a3,
    uint32_t b0, uint32_t b1)
{
    asm volatile(
        "mma.sync.aligned.m16n8k8.row.col.f32.tf32.tf32.f32 "
        "{%0,%1,%2,%3},{%4,%5,%6,%7},{%8,%9},{%0,%1,%2,%3};"
        : "+f"(d[0]), "+f"(d[1]), "+f"(d[2]), "+f"(d[3])
        : "r"(a0), "r"(a1), "r"(a2), "r"(a3), "r"(b0), "r"(b1));
}

// ===========================================================================
// Tensor GEMM, ABT form: C[M,N] = A[M,K] * B[N,K]^T
// BM=BN=64, BK=16, 256 threads (8 warps: 2 in m x 4 in n), warp tile 32x16.
// SPLIT: 2-term tf32 decomposition (3 mma products) for ~fp32 accuracy.
// z: generic offset (batch OR k-split) via element strides sAz/sBz/sCz.
// ===========================================================================
template<bool SPLIT>
__global__ void __launch_bounds__(256)
tgemm_abt(const float* __restrict__ Ag, int lda, long sAz,
          const float* __restrict__ Bg, int ldb, long sBz,
          float* __restrict__ Cg, int ldc, long sCz,
          int K)
{
    constexpr int NP = SPLIT ? 2 : 1;
    constexpr int BK = 16, LDT = 64 + 4;
    __shared__ float As[NP][BK][LDT];
    __shared__ float Bs[NP][BK][LDT];

    const int z = blockIdx.z;
    Ag += (long)z * sAz;  Bg += (long)z * sBz;  Cg += (long)z * sCz;
    const int m0 = blockIdx.y * 64, n0 = blockIdx.x * 64;
    const int tid = threadIdx.x, lane = tid & 31, wid = tid >> 5;
    const int wm0 = (wid & 1) * 32, wn0 = (wid >> 1) * 16;
    const int r4 = lane >> 2, c4 = lane & 3;
    const int arow = tid >> 2, ac4 = (tid & 3) * 4;

    float acc[2][2][4] = {};

    for (int k0 = 0; k0 < K; k0 += BK) {
        // A tile 64x16 -> As[k][m] (hi/lo planes)
        {
            float4 v = *(const float4*)(Ag + (long)(m0 + arow) * lda + k0 + ac4);
            #pragma unroll
            for (int j = 0; j < 4; j++) {
                float x = (&v.x)[j];
                float h = tf32_rna(x);
                As[0][ac4 + j][arow] = h;
                if (SPLIT) As[NP-1][ac4 + j][arow] = tf32_rna(x - h);
            }
            float4 w = *(const float4*)(Bg + (long)(n0 + arow) * ldb + k0 + ac4);
            #pragma unroll
            for (int j = 0; j < 4; j++) {
                float x = (&w.x)[j];
                float h = tf32_rna(x);
                Bs[0][ac4 + j][arow] = h;
                if (SPLIT) Bs[NP-1][ac4 + j][arow] = tf32_rna(x - h);
            }
        }
        __syncthreads();
        #pragma unroll
        for (int pp = 0; pp < (SPLIT ? 3 : 1); pp++) {
            const int pa = (pp == 2) ? NP-1 : 0;
            const int pb = (pp == 1) ? NP-1 : 0;
            #pragma unroll
            for (int kk = 0; kk < BK; kk += 8) {
                uint32_t af[2][4], bf[2][2];
                #pragma unroll
                for (int mt = 0; mt < 2; mt++) {
                    int row = wm0 + mt*16 + r4;
                    af[mt][0] = f2u(As[pa][kk + c4    ][row    ]);
                    af[mt][1] = f2u(As[pa][kk + c4    ][row + 8]);
                    af[mt][2] = f2u(As[pa][kk + c4 + 4][row    ]);
                    af[mt][3] = f2u(As[pa][kk + c4 + 4][row + 8]);
                }
                #pragma unroll
                for (int nt = 0; nt < 2; nt++) {
                    int col = wn0 + nt*8 + r4;
                    bf[nt][0] = f2u(Bs[pb][kk + c4    ][col]);
                    bf[nt][1] = f2u(Bs[pb][kk + c4 + 4][col]);
                }
                #pragma unroll
                for (int mt = 0; mt < 2; mt++)
                    #pragma unroll
                    for (int nt = 0; nt < 2; nt++)
                        mma_tf32(acc[mt][nt], af[mt][0], af[mt][1], af[mt][2], af[mt][3],
                                 bf[nt][0], bf[nt][1]);
            }
        }
        __syncthreads();
    }
    #pragma unroll
    for (int mt = 0; mt < 2; mt++)
        #pragma unroll
        for (int nt = 0; nt < 2; nt++) {
            int row = m0 + wm0 + mt*16 + r4;
            int col = n0 + wn0 + nt*8 + 2*c4;
            *(float2*)(Cg + (long)row * ldc + col) =
                make_float2(acc[mt][nt][0], acc[mt][nt][1]);
            *(float2*)(Cg + (long)(row + 8) * ldc + col) =
                make_float2(acc[mt][nt][2], acc[mt][nt][3]);
        }
}

// ===========================================================================
// Tensor GEMM, ATB form: C[64,N] = A[L,64]^T * B[L,N], reduction over rows L.
// grid: (N/64, NSPLIT, batch). Per block: L-chunk of Lchunk rows.
// ===========================================================================
template<bool SPLIT>
__global__ void __launch_bounds__(256)
tgemm_atb(const float* __restrict__ Ag, int lda, long sAb,
          const float* __restrict__ Bg, int ldb, long sBb,
          float* __restrict__ Cg, long sCb, long sCsplit, int ldc,
          int Lchunk)
{
    constexpr int NP = SPLIT ? 2 : 1;
    constexpr int BK = 16, LDT = 64 + 4;
    __shared__ float As[NP][BK][LDT];
    __shared__ float Bs[NP][BK][LDT];

    const int b = blockIdx.z, sp = blockIdx.y;
    const long l0b = (long)sp * Lchunk;
    Ag += (long)b * sAb;  Bg += (long)b * sBb;
    Cg += (long)b * sCb + (long)sp * sCsplit;
    const int n0 = blockIdx.x * 64;
    const int tid = threadIdx.x, lane = tid & 31, wid = tid >> 5;
    const int wm0 = (wid & 1) * 32, wn0 = (wid >> 1) * 16;
    const int r4 = lane >> 2, c4 = lane & 3;
    const int lrow = tid >> 4, lc4 = (tid & 15) * 4;

    float acc[2][2][4] = {};

    for (int l0 = 0; l0 < Lchunk; l0 += BK) {
        // A tile [16 L-rows x 64 m-cols] -> As[k][m] (already k-major)
        {
            float4 v = *(const float4*)(Ag + (l0b + l0 + lrow) * lda + lc4);
            #pragma unroll
            for (int j = 0; j < 4; j++) {
                float x = (&v.x)[j];
                float h = tf32_rna(x);
                As[0][lrow][lc4 + j] = h;
                if (SPLIT) As[NP-1][lrow][lc4 + j] = tf32_rna(x - h);
            }
            float4 w = *(const float4*)(Bg + (l0b + l0 + lrow) * ldb + n0 + lc4);
            #pragma unroll
            for (int j = 0; j < 4; j++) {
                float x = (&w.x)[j];
                float h = tf32_rna(x);
                Bs[0][lrow][lc4 + j] = h;
                if (SPLIT) Bs[NP-1][lrow][lc4 + j] = tf32_rna(x - h);
            }
        }
        __syncthreads();
        #pragma unroll
        for (int pp = 0; pp < (SPLIT ? 3 : 1); pp++) {
            const int pa = (pp == 2) ? NP-1 : 0;
            const int pb = (pp == 1) ? NP-1 : 0;
            #pragma unroll
            for (int kk = 0; kk < BK; kk += 8) {
                uint32_t af[2][4], bf[2][2];
                #pragma unroll
                for (int mt = 0; mt < 2; mt++) {
                    int row = wm0 + mt*16 + r4;
                    af[mt][0] = f2u(As[pa][kk + c4    ][row    ]);
                    af[mt][1] = f2u(As[pa][kk + c4    ][row + 8]);
                    af[mt][2] = f2u(As[pa][kk + c4 + 4][row    ]);
                    af[mt][3] = f2u(As[pa][kk + c4 + 4][row + 8]);
                }
                #pragma unroll
                for (int nt = 0; nt < 2; nt++) {
                    int col = wn0 + nt*8 + r4;
                    bf[nt][0] = f2u(Bs[pb][kk + c4    ][col]);
                    bf[nt][1] = f2u(Bs[pb][kk + c4 + 4][col]);
                }
                #pragma unroll
                for (int mt = 0; mt < 2; mt++)
                    #pragma unroll
                    for (int nt = 0; nt < 2; nt++)
                        mma_tf32(acc[mt][nt], af[mt][0], af[mt][1], af[mt][2], af[mt][3],
                                 bf[nt][0], bf[nt][1]);
            }
        }
        __syncthreads();
    }
    #pragma unroll
    for (int mt = 0; mt < 2; mt++)
        #pragma unroll
        for (int nt = 0; nt < 2; nt++) {
            int row = wm0 + mt*16 + r4;
            int col = n0 + wn0 + nt*8 + 2*c4;
            *(float2*)(Cg + (long)row * ldc + col) =
                make_float2(acc[mt][nt][0], acc[mt][nt][1]);
            *(float2*)(Cg + (long)(row + 8) * ldc + col) =
                make_float2(acc[mt][nt][2], acc[mt][nt][3]);
        }
}

// ===========================================================================
// SIMT fp32 NN GEMM (kept for small steps): C[M,N] = A[M,K]*B[K,N] (+Cadd)
// ===========================================================================
template<int BM,int BN,int BK,int TM,int TN,bool ADD>
__global__ void __launch_bounds__((BM/TM)*(BN/TN))
gemm_nn(const float* __restrict__ A, long sA, int lda,
        const float* __restrict__ B, long sB, int ldb,
        const float* __restrict__ Cadd, long sAdd, int ldadd,
        float* __restrict__ C, long sC, int ldc,
        int K)
{
    constexpr int THREADS = (BM/TM)*(BN/TN);
    __shared__ float As[BK][BM];
    __shared__ float Bs[BK][BN];

    const int bz = blockIdx.z;
    A += bz * sA;  B += bz * sB;  C += bz * sC;
    const float* Cad = ADD ? (Cadd + bz * sAdd) : nullptr;

    const int m0 = blockIdx.y * BM;
    const int n0 = blockIdx.x * BN;
    const int tid = threadIdx.x;
    const int tx = tid % (BN/TN);
    const int ty = tid / (BN/TN);

    float acc[TM][TN];
    #pragma unroll
    for (int i = 0; i < TM; i++)
        #pragma unroll
        for (int j = 0; j < TN; j++) acc[i][j] = 0.f;

    for (int k0 = 0; k0 < K; k0 += BK) {
        #pragma unroll
        for (int e = 0; e < (BM*BK/4)/THREADS; e++) {
            int idx = tid + e*THREADS;
            int row = idx / (BK/4), cv = idx % (BK/4);
            float4 v = *(const float4*)(A + (long)(m0+row)*lda + k0 + cv*4);
            As[cv*4+0][row] = v.x;  As[cv*4+1][row] = v.y;
            As[cv*4+2][row] = v.z;  As[cv*4+3][row] = v.w;
        }
        #pragma unroll
        for (int e = 0; e < (BK*BN/4)/THREADS; e++) {
            int idx = tid + e*THREADS;
            int row = idx / (BN/4), cv = idx % (BN/4);
            *(float4*)&Bs[row][cv*4] =
                *(const float4*)(B + (long)(k0+row)*ldb + n0 + cv*4);
        }
        __syncthreads();
        #pragma unroll
        for (int k = 0; k < BK; k++) {
            float a[TM], b[TN];
            #pragma unroll
            for (int i = 0; i < TM; i += 4) *(float4*)(a+i) = *(const float4*)&As[k][ty*TM+i];
            #pragma unroll
            for (int j = 0; j < TN; j += 4) *(float4*)(b+j) = *(const float4*)&Bs[k][tx*TN+j];
            #pragma unroll
            for (int i = 0; i < TM; i++)
                #pragma unroll
                for (int j = 0; j < TN; j++) acc[i][j] += a[i]*b[j];
        }
        __syncthreads();
    }
    #pragma unroll
    for (int i = 0; i < TM; i++) {
        int row = m0 + ty*TM + i;
        #pragma unroll
        for (int j = 0; j < TN; j += 4) {
            float4 v;
            v.x = acc[i][j];   v.y = acc[i][j+1];
            v.z = acc[i][j+2]; v.w = acc[i][j+3];
            if (ADD) {
                float4 c = *(const float4*)(Cad + (long)row*ldadd + n0 + tx*TN + j);
                v.x += c.x; v.y += c.y; v.z += c.z; v.w += c.w;
            }
            *(float4*)(C + (long)row*ldc + n0 + tx*TN + j) = v;
        }
    }
}

// Sum S split partials
template<int S>
__global__ void reduceN(const float* __restrict__ p, float* __restrict__ o, int n)
{
    int i = blockIdx.x * 256 + threadIdx.x;
    if (i < n) {
        float s = 0.f;
        #pragma unroll
        for (int j = 0; j < S; j++) s += p[i + (long)j * n];
        o[i] = s;
    }
}

// ============================================================================
extern "C" void kernel_launch(void* const* d_in, const int* in_sizes, int n_in,
                              void* d_out, int out_size)
{
    const float* x  = (const float*)d_in[0];   // [8,2048,1024]
    const float* Wq = (const float*)d_in[1];   // [64,1024]
    const float* Wk = (const float*)d_in[2];   // [64,1024]
    const float* Wv = (const float*)d_in[3];   // [1024,1024]
    const float* W1 = (const float*)d_in[4];   // [64,1024]
    const float* W2 = (const float*)d_in[5];   // [1024,64]
    float* out = (float*)d_out;                // [8,2048,1024]

    float *wcat, *qkf, *apart, *ga, *u2p, *u2, *gt, *gfc;
    cudaGetSymbolAddress((void**)&wcat, g_Wcat);
    cudaGetSymbolAddress((void**)&qkf,  g_QKF);
    cudaGetSymbolAddress((void**)&apart,g_Apart);
    cudaGetSymbolAddress((void**)&ga,   g_A);
    cudaGetSymbolAddress((void**)&u2p,  g_U2part);
    cudaGetSymbolAddress((void**)&u2,   g_U2);
    cudaGetSymbolAddress((void**)&gt,   g_T);
    cudaGetSymbolAddress((void**)&gfc,  g_fc);

    // Stack [Wq; Wk; W1] -> g_Wcat
    cudaMemcpyAsync(wcat,            Wq, (size_t)DKK*DD*sizeof(float), cudaMemcpyDeviceToDevice);
    cudaMemcpyAsync(wcat + DKK*DD,   Wk, (size_t)DKK*DD*sizeof(float), cudaMemcpyDeviceToDevice);
    cudaMemcpyAsync(wcat + 2*DKK*DD, W1, (size_t)DKK*DD*sizeof(float), cudaMemcpyDeviceToDevice);

    // 1) QKF = x @ Wcat^T : [16384,192]  (tensor, split-tf32 for accuracy on F)
    tgemm_abt<true><<<dim3(3, 256, 1), 256>>>(
        x, DD, 0,  wcat, DD, 0,  qkf, 192, 0,  DD);

    // 2) A_b = K_b^T x_b : [8,64,1024]  (tensor, single tf32; 4-way L-split)
    tgemm_atb<false><<<dim3(16, 4, 8), 256>>>(
        qkf + 64, 192, (long)NSEQ*192,
        x,        DD,  (long)NSEQ*DD,
        apart, (long)DKK*DD, (long)BB*DKK*DD, DD,
        NSEQ/4);
    reduceN<4><<<(BB*DKK*DD + 255)/256, 256>>>(apart, ga, BB*DKK*DD);

    // 3) U2 = W1 @ Wv : [64,1024]  (SIMT fp32, 8-way split-K for occupancy)
    gemm_nn<64,64,16,4,4,false><<<dim3(16,1,8), 256>>>(
        W1, 128, DD,  Wv, (long)128*DD, DD,  nullptr, 0, 0,
        u2p, (long)DKK*DD, DD,  128);
    reduceN<8><<<(DKK*DD + 255)/256, 256>>>(u2p, u2, DKK*DD);

    // 4) T_b = A_b @ U2^T : [8,64,64]  (tensor, single tf32)
    tgemm_abt<false><<<dim3(1, 1, 8), 256>>>(
        ga, DD, (long)DKK*DD,  u2, DD, 0,  gt, DKK, (long)DKK*DKK,  DD);

    // 5) fc_b = F_b + Q_b @ T_b : [8,2048,64]  (SIMT fp32, small K=64)
    gemm_nn<64,64,16,4,4,true><<<dim3(1, 32, 8), 256>>>(
        qkf,       (long)NSEQ*192, 192,
        gt,        (long)DKK*DKK,  DKK,
        qkf + 128, (long)NSEQ*192, 192,
        gfc,       (long)NSEQ*DKK, DKK,
        DKK);

    // 6) out = fc @ W2^T : [16384,1024]  (tensor, split-tf32 for accuracy)
    tgemm_abt<true><<<dim3(16, 256, 1), 256>>>(
        gfc, DKK, 0,  W2, DKK, 0,  out, DD, 0,  DKK);
}

// round 3
// speedup vs baseline: 2.0278x; 1.8779x over previous
#include <cuda_runtime.h>
#include <cuda_bf16.h>
#include <cstdint>

// Problem dims (fixed by the dataset)
#define BB 8
#define NSEQ 2048
#define DD 1024
#define DKK 64
#define MTOT (BB*NSEQ)   // 16384

// ---------------- scratch (static __device__ — no allocation) ----------------
__device__ float g_Wext[256*DD];            // [Wq;Wk;W1;U2] stacked, 256x1024
__device__ float g_QKFP[(long)MTOT*256];    // per row: Q[0:64] K[64:128] F[128:192] P[192:256]
__device__ float g_U2part[16*DKK*DD];       // split-K partials of U2
__device__ float g_Tpart[4*BB*DKK*DKK];     // split-L partials of T
__device__ float g_T[BB*DKK*DKK];           // T_b = K_b^T P_b
__device__ float g_fc[MTOT*DKK];            // fc = F + Q @ T

// ---------------------------------------------------------------------------
// helpers
// ---------------------------------------------------------------------------
__device__ __forceinline__ float tf32_rna(float x) {
    uint32_t r;
    asm("cvt.rna.tf32.f32 %0, %1;" : "=r"(r) : "f"(x));
    return __uint_as_float(r);
}
__device__ __forceinline__ uint32_t f2u(float f) { return __float_as_uint(f); }

__device__ __forceinline__ void mma_tf32(float (&d)[4],
    uint32_t a0, uint32_t a1, uint32_t a2, uint32_t a3,
    uint32_t b0, uint32_t b1)
{
    asm volatile(
        "mma.sync.aligned.m16n8k8.row.col.f32.tf32.tf32.f32 "
        "{%0,%1,%2,%3},{%4,%5,%6,%7},{%8,%9},{%0,%1,%2,%3};"
        : "+f"(d[0]), "+f"(d[1]), "+f"(d[2]), "+f"(d[3])
        : "r"(a0), "r"(a1), "r"(a2), "r"(a3), "r"(b0), "r"(b1));
}

__device__ __forceinline__ void mma_bf16(float (&d)[4],
    const uint32_t (&a)[4], const uint32_t (&b)[2])
{
    asm volatile(
        "mma.sync.aligned.m16n8k16.row.col.f32.bf16.bf16.f32 "
        "{%0,%1,%2,%3},{%4,%5,%6,%7},{%8,%9},{%0,%1,%2,%3};"
        : "+f"(d[0]), "+f"(d[1]), "+f"(d[2]), "+f"(d[3])
        : "r"(a[0]), "r"(a[1]), "r"(a[2]), "r"(a[3]), "r"(b[0]), "r"(b[1]));
}

// ===========================================================================
// bf16-split tensor GEMM, ABT form: C[M,N] = A[M,K] * B[N,K]^T (fp32 in/out)
// A,B converted on the fly to bf16 hi/lo planes; 3 products (hh, hl, lh)
// reconstruct ~fp32 accuracy. BM=128, BN=64, BK=32.
// 256 threads = 8 warps (2 m x 4 n), warp tile 64x16, per-warp 4x2 mma tiles.
// Smem rows padded to 20 uint32 (80B) -> conflict-free fragment reads.
// ===========================================================================
__global__ void __launch_bounds__(256)
tbgemm_abt(const float* __restrict__ Ag, int lda,
           const float* __restrict__ Bg, int ldb,
           float* __restrict__ Cg, int ldc, int K)
{
    constexpr int SP = 20;  // uint32 per smem row (16 k-pairs + 4 pad)
    __shared__ uint32_t Ah[128*SP], Al[128*SP];
    __shared__ uint32_t Bh[64*SP],  Bl[64*SP];

    const int m0 = blockIdx.y * 128, n0 = blockIdx.x * 64;
    const int tid = threadIdx.x, lane = tid & 31, wid = tid >> 5;
    const int wm0 = (wid & 1) * 64, wn0 = (wid >> 1) * 16;
    const int r4 = lane >> 2, c4 = lane & 3;

    float acc[4][2][4] = {};

    for (int k0 = 0; k0 < K; k0 += 32) {
        // ---- A tile 128x32 fp32 -> hi/lo bf16 pairs ----
        #pragma unroll
        for (int e = 0; e < 4; e++) {
            int idx = tid + e * 256;          // 1024 float4 slots
            int row = idx >> 3, fq = idx & 7; // 8 float4 per row
            float4 v = *(const float4*)(Ag + (long)(m0 + row) * lda + k0 + fq * 4);
            __nv_bfloat162 h0 = __floats2bfloat162_rn(v.x, v.y);
            __nv_bfloat162 h1 = __floats2bfloat162_rn(v.z, v.w);
            __nv_bfloat162 l0 = __floats2bfloat162_rn(v.x - __bfloat162float(h0.x),
                                                      v.y - __bfloat162float(h0.y));
            __nv_bfloat162 l1 = __floats2bfloat162_rn(v.z - __bfloat162float(h1.x),
                                                      v.w - __bfloat162float(h1.y));
            int o = row * SP + fq * 2;
            *reinterpret_cast<__nv_bfloat162*>(&Ah[o])     = h0;
            *reinterpret_cast<__nv_bfloat162*>(&Ah[o + 1]) = h1;
            *reinterpret_cast<__nv_bfloat162*>(&Al[o])     = l0;
            *reinterpret_cast<__nv_bfloat162*>(&Al[o + 1]) = l1;
        }
        // ---- B tile 64x32 fp32 -> hi/lo bf16 pairs ----
        #pragma unroll
        for (int e = 0; e < 2; e++) {
            int idx = tid + e * 256;          // 512 float4 slots
            int row = idx >> 3, fq = idx & 7;
            float4 v = *(const float4*)(Bg + (long)(n0 + row) * ldb + k0 + fq * 4);
            __nv_bfloat162 h0 = __floats2bfloat162_rn(v.x, v.y);
            __nv_bfloat162 h1 = __floats2bfloat162_rn(v.z, v.w);
            __nv_bfloat162 l0 = __floats2bfloat162_rn(v.x - __bfloat162float(h0.x),
                                                      v.y - __bfloat162float(h0.y));
            __nv_bfloat162 l1 = __floats2bfloat162_rn(v.z - __bfloat162float(h1.x),
                                                      v.w - __bfloat162float(h1.y));
            int o = row * SP + fq * 2;
            *reinterpret_cast<__nv_bfloat162*>(&Bh[o])     = h0;
            *reinterpret_cast<__nv_bfloat162*>(&Bh[o + 1]) = h1;
            *reinterpret_cast<__nv_bfloat162*>(&Bl[o])     = l0;
            *reinterpret_cast<__nv_bfloat162*>(&Bl[o + 1]) = l1;
        }
        __syncthreads();

        #pragma unroll
        for (int kp = 0; kp < 16; kp += 8) {   // two k16 steps per BK=32
            uint32_t ah[4][4], al[4][4], bh[2][2], bl[2][2];
            #pragma unroll
            for (int mt = 0; mt < 4; mt++) {
                int r = (wm0 + mt * 16 + r4) * SP + kp + c4;
                ah[mt][0] = Ah[r];          ah[mt][1] = Ah[r + 8*SP];
                ah[mt][2] = Ah[r + 4];      ah[mt][3] = Ah[r + 8*SP + 4];
                al[mt][0] = Al[r];          al[mt][1] = Al[r + 8*SP];
                al[mt][2] = Al[r + 4];      al[mt][3] = Al[r + 8*SP + 4];
            }
            #pragma unroll
            for (int nt = 0; nt < 2; nt++) {
                int r = (wn0 + nt * 8 + r4) * SP + kp + c4;
                bh[nt][0] = Bh[r];  bh[nt][1] = Bh[r + 4];
                bl[nt][0] = Bl[r];  bl[nt][1] = Bl[r + 4];
            }
            #pragma unroll
            for (int mt = 0; mt < 4; mt++)
                #pragma unroll
                for (int nt = 0; nt < 2; nt++) {
                    mma_bf16(acc[mt][nt], ah[mt], bh[nt]);  // hi*hi
                    mma_bf16(acc[mt][nt], ah[mt], bl[nt]);  // hi*lo
                    mma_bf16(acc[mt][nt], al[mt], bh[nt]);  // lo*hi
                }
        }
        __syncthreads();
    }

    #pragma unroll
    for (int mt = 0; mt < 4; mt++)
        #pragma unroll
        for (int nt = 0; nt < 2; nt++) {
            int row = m0 + wm0 + mt * 16 + r4;
            int col = n0 + wn0 + nt * 8 + 2 * c4;
            *(float2*)(Cg + (long)row * ldc + col) =
                make_float2(acc[mt][nt][0], acc[mt][nt][1]);
            *(float2*)(Cg + (long)(row + 8) * ldc + col) =
                make_float2(acc[mt][nt][2], acc[mt][nt][3]);
        }
}

// ===========================================================================
// Tensor GEMM (tf32), ATB form: C[64,N] = A[L,64]^T * B[L,N] over rows L.
// grid: (N/64, NSPLIT, batch). Validated in round 2.
// ===========================================================================
__global__ void __launch_bounds__(256)
tgemm_atb(const float* __restrict__ Ag, int lda, long sAb,
          const float* __restrict__ Bg, int ldb, long sBb,
          float* __restrict__ Cg, long sCb, long sCsplit, int ldc,
          int Lchunk)
{
    constexpr int BK = 16, LDT = 64 + 4;
    __shared__ float As[BK][LDT];
    __shared__ float Bs[BK][LDT];

    const int b = blockIdx.z, sp = blockIdx.y;
    const long l0b = (long)sp * Lchunk;
    Ag += (long)b * sAb;  Bg += (long)b * sBb;
    Cg += (long)b * sCb + (long)sp * sCsplit;
    const int n0 = blockIdx.x * 64;
    const int tid = threadIdx.x, lane = tid & 31, wid = tid >> 5;
    const int wm0 = (wid & 1) * 32, wn0 = (wid >> 1) * 16;
    const int r4 = lane >> 2, c4 = lane & 3;
    const int lrow = tid >> 4, lc4 = (tid & 15) * 4;

    float acc[2][2][4] = {};

    for (int l0 = 0; l0 < Lchunk; l0 += BK) {
        {
            float4 v = *(const float4*)(Ag + (l0b + l0 + lrow) * lda + lc4);
            As[lrow][lc4+0] = tf32_rna(v.x);  As[lrow][lc4+1] = tf32_rna(v.y);
            As[lrow][lc4+2] = tf32_rna(v.z);  As[lrow][lc4+3] = tf32_rna(v.w);
            float4 w = *(const float4*)(Bg + (l0b + l0 + lrow) * ldb + n0 + lc4);
            Bs[lrow][lc4+0] = tf32_rna(w.x);  Bs[lrow][lc4+1] = tf32_rna(w.y);
            Bs[lrow][lc4+2] = tf32_rna(w.z);  Bs[lrow][lc4+3] = tf32_rna(w.w);
        }
        __syncthreads();
        #pragma unroll
        for (int kk = 0; kk < BK; kk += 8) {
            uint32_t af[2][4], bf[2][2];
            #pragma unroll
            for (int mt = 0; mt < 2; mt++) {
                int row = wm0 + mt*16 + r4;
                af[mt][0] = f2u(As[kk + c4    ][row    ]);
                af[mt][1] = f2u(As[kk + c4    ][row + 8]);
                af[mt][2] = f2u(As[kk + c4 + 4][row    ]);
                af[mt][3] = f2u(As[kk + c4 + 4][row + 8]);
            }
            #pragma unroll
            for (int nt = 0; nt < 2; nt++) {
                int col = wn0 + nt*8 + r4;
                bf[nt][0] = f2u(Bs[kk + c4    ][col]);
                bf[nt][1] = f2u(Bs[kk + c4 + 4][col]);
            }
            #pragma unroll
            for (int mt = 0; mt < 2; mt++)
                #pragma unroll
                for (int nt = 0; nt < 2; nt++)
                    mma_tf32(acc[mt][nt], af[mt][0], af[mt][1], af[mt][2], af[mt][3],
                             bf[nt][0], bf[nt][1]);
        }
        __syncthreads();
    }
    #pragma unroll
    for (int mt = 0; mt < 2; mt++)
        #pragma unroll
        for (int nt = 0; nt < 2; nt++) {
            int row = wm0 + mt*16 + r4;
            int col = n0 + wn0 + nt*8 + 2*c4;
            *(float2*)(Cg + (long)row * ldc + col) =
                make_float2(acc[mt][nt][0], acc[mt][nt][1]);
            *(float2*)(Cg + (long)(row + 8) * ldc + col) =
                make_float2(acc[mt][nt][2], acc[mt][nt][3]);
        }
}

// ===========================================================================
// SIMT fp32 NN GEMM (U2 only): C[M,N] = A[M,K]*B[K,N], split-K via z
// ===========================================================================
template<int BM,int BN,int BK,int TM,int TN>
__global__ void __launch_bounds__((BM/TM)*(BN/TN))
gemm_nn(const float* __restrict__ A, long sA, int lda,
        const float* __restrict__ B, long sB, int ldb,
        float* __restrict__ C, long sC, int ldc,
        int K)
{
    constexpr int THREADS = (BM/TM)*(BN/TN);
    __shared__ float As[BK][BM];
    __shared__ float Bs[BK][BN];

    const int bz = blockIdx.z;
    A += bz * sA;  B += bz * sB;  C += bz * sC;

    const int m0 = blockIdx.y * BM;
    const int n0 = blockIdx.x * BN;
    const int tid = threadIdx.x;
    const int tx = tid % (BN/TN);
    const int ty = tid / (BN/TN);

    float acc[TM][TN];
    #pragma unroll
    for (int i = 0; i < TM; i++)
        #pragma unroll
        for (int j = 0; j < TN; j++) acc[i][j] = 0.f;

    for (int k0 = 0; k0 < K; k0 += BK) {
        #pragma unroll
        for (int e = 0; e < (BM*BK/4)/THREADS; e++) {
            int idx = tid + e*THREADS;
            int row = idx / (BK/4), cv = idx % (BK/4);
            float4 v = *(const float4*)(A + (long)(m0+row)*lda + k0 + cv*4);
            As[cv*4+0][row] = v.x;  As[cv*4+1][row] = v.y;
            As[cv*4+2][row] = v.z;  As[cv*4+3][row] = v.w;
        }
        #pragma unroll
        for (int e = 0; e < (BK*BN/4)/THREADS; e++) {
            int idx = tid + e*THREADS;
            int row = idx / (BN/4), cv = idx % (BN/4);
            *(float4*)&Bs[row][cv*4] =
                *(const float4*)(B + (long)(k0+row)*ldb + n0 + cv*4);
        }
        __syncthreads();
        #pragma unroll
        for (int k = 0; k < BK; k++) {
            float a[TM], b[TN];
            #pragma unroll
            for (int i = 0; i < TM; i += 4) *(float4*)(a+i) = *(const float4*)&As[k][ty*TM+i];
            #pragma unroll
            for (int j = 0; j < TN; j += 4) *(float4*)(b+j) = *(const float4*)&Bs[k][tx*TN+j];
            #pragma unroll
            for (int i = 0; i < TM; i++)
                #pragma unroll
                for (int j = 0; j < TN; j++) acc[i][j] += a[i]*b[j];
        }
        __syncthreads();
    }
    #pragma unroll
    for (int i = 0; i < TM; i++) {
        int row = m0 + ty*TM + i;
        #pragma unroll
        for (int j = 0; j < TN; j += 4) {
            float4 v;
            v.x = acc[i][j];   v.y = acc[i][j+1];
            v.z = acc[i][j+2]; v.w = acc[i][j+3];
            *(float4*)(C + (long)row*ldc + n0 + tx*TN + j) = v;
        }
    }
}

// Sum S split partials
template<int S>
__global__ void reduceN(const float* __restrict__ p, float* __restrict__ o, int n)
{
    int i = blockIdx.x * 256 + threadIdx.x;
    if (i < n) {
        float s = 0.f;
        #pragma unroll
        for (int j = 0; j < S; j++) s += p[i + (long)j * n];
        o[i] = s;
    }
}

// ===========================================================================
// fc = F + Q @ T_b : per block 64 rows (one batch), fp32 exact.
// qkfp row: Q at +0, F at +128. Output fc [MTOT x 64] fp32.
// ===========================================================================
__global__ void __launch_bounds__(256)
fc_kernel(const float* __restrict__ qkfp, const float* __restrict__ T,
          float* __restrict__ fc)
{
    __shared__ float Qs[64][68];
    __shared__ float Ts[64][68];

    const int r0 = blockIdx.x * 64;       // 64 rows, same batch (2048 % 64 == 0)
    const int b  = r0 / NSEQ;
    const int tid = threadIdx.x;

    // load Q rows and T_b
    #pragma unroll
    for (int e = 0; e < 4; e++) {
        int idx = tid + e * 256;          // 1024 float4 slots
        int row = idx >> 4, fq = idx & 15;
        float4 q = *(const float4*)(qkfp + (long)(r0 + row) * 256 + fq * 4);
        *(float4*)&Qs[row][fq * 4] = q;
        float4 t = *(const float4*)(T + (long)b * 4096 + row * 64 + fq * 4);
        *(float4*)&Ts[row][fq * 4] = t;
    }
    __syncthreads();

    const int row = tid >> 2;
    const int col0 = (tid & 3) * 16;
    float acc[16];
    #pragma unroll
    for (int j = 0; j < 16; j += 4) {
        float4 f = *(const float4*)(qkfp + (long)(r0 + row) * 256 + 128 + col0 + j);
        acc[j] = f.x; acc[j+1] = f.y; acc[j+2] = f.z; acc[j+3] = f.w;
    }
    #pragma unroll 8
    for (int k = 0; k < 64; k++) {
        float q = Qs[row][k];
        #pragma unroll
        for (int j = 0; j < 16; j += 4) {
            float4 t = *(const float4*)&Ts[k][col0 + j];
            acc[j]   += q * t.x;  acc[j+1] += q * t.y;
            acc[j+2] += q * t.z;  acc[j+3] += q * t.w;
        }
    }
    #pragma unroll
    for (int j = 0; j < 16; j += 4) {
        float4 v; v.x = acc[j]; v.y = acc[j+1]; v.z = acc[j+2]; v.w = acc[j+3];
        *(float4*)(fc + (long)(r0 + row) * 64 + col0 + j) = v;
    }
}

// ============================================================================
extern "C" void kernel_launch(void* const* d_in, const int* in_sizes, int n_in,
                              void* d_out, int out_size)
{
    const float* x  = (const float*)d_in[0];   // [8,2048,1024]
    const float* Wq = (const float*)d_in[1];   // [64,1024]
    const float* Wk = (const float*)d_in[2];   // [64,1024]
    const float* Wv = (const float*)d_in[3];   // [1024,1024]
    const float* W1 = (const float*)d_in[4];   // [64,1024]
    const float* W2 = (const float*)d_in[5];   // [1024,64]
    float* out = (float*)d_out;                // [8,2048,1024]

    float *wext, *qkfp, *u2p, *tpart, *gt, *gfc;
    cudaGetSymbolAddress((void**)&wext,  g_Wext);
    cudaGetSymbolAddress((void**)&qkfp,  g_QKFP);
    cudaGetSymbolAddress((void**)&u2p,   g_U2part);
    cudaGetSymbolAddress((void**)&tpart, g_Tpart);
    cudaGetSymbolAddress((void**)&gt,    g_T);
    cudaGetSymbolAddress((void**)&gfc,   g_fc);

    // Stack [Wq; Wk; W1] -> g_Wext rows 0..191
    cudaMemcpyAsync(wext,            Wq, (size_t)DKK*DD*sizeof(float), cudaMemcpyDeviceToDevice);
    cudaMemcpyAsync(wext + DKK*DD,   Wk, (size_t)DKK*DD*sizeof(float), cudaMemcpyDeviceToDevice);
    cudaMemcpyAsync(wext + 2*DKK*DD, W1, (size_t)DKK*DD*sizeof(float), cudaMemcpyDeviceToDevice);

    // U2 = W1 @ Wv : [64,1024], 16-way split-K, written into g_Wext rows 192..255
    gemm_nn<64,64,16,4,4><<<dim3(16,1,16), 256>>>(
        W1, 64, DD,  Wv, (long)64*DD, DD,  u2p, (long)DKK*DD, DD,  64);
    reduceN<16><<<(DKK*DD + 255)/256, 256>>>(u2p, wext + (long)192*DD, DKK*DD);

    // QKFP = x @ Wext^T : [16384,256]  (bf16-split tensor GEMM)
    tbgemm_abt<<<dim3(4, 128), 256>>>(x, DD, wext, DD, qkfp, 256, DD);

    // T_b = K_b^T P_b : [8,64,64]  (tf32, 4-way L-split) + reduce
    tgemm_atb<<<dim3(1, 4, 8), 256>>>(
        qkfp + 64,  256, (long)NSEQ*256,
        qkfp + 192, 256, (long)NSEQ*256,
        tpart, (long)DKK*DKK, (long)BB*DKK*DKK, DKK,
        NSEQ/4);
    reduceN<4><<<(BB*DKK*DKK + 255)/256, 256>>>(tpart, gt, BB*DKK*DKK);

    // fc = F + Q @ T : [16384,64] fp32
    fc_kernel<<<MTOT/64, 256>>>(qkfp, gt, gfc);

    // out = fc @ W2^T : [16384,1024]  (bf16-split tensor GEMM)
    tbgemm_abt<<<dim3(16, 128), 256>>>(gfc, DKK, W2, DKK, out, DD, DKK);
}

// round 4
// speedup vs baseline: 2.6436x; 1.3036x over previous
#include <cuda_runtime.h>
#include <cuda_bf16.h>
#include <cstdint>

// Problem dims (fixed by the dataset)
#define BB 8
#define NSEQ 2048
#define DD 1024
#define DKK 64
#define MTOT (BB*NSEQ)   // 16384

// ---------------- scratch (static __device__ — no allocation) ----------------
__device__ float g_Wext[256*DD];            // [Wq;Wk;W1;U2] stacked, 256x1024
__device__ float g_QKFP[(long)MTOT*256];    // per row: Q[0:64] K[64:128] F[128:192] P[192:256]
__device__ float g_U2part[32*DKK*DD];       // split-K partials of U2
__device__ float g_Tpart[32*BB*DKK*DKK];    // split-L partials of T
__device__ float g_T[BB*DKK*DKK];           // T_b = K_b^T P_b
__device__ float g_fc[MTOT*DKK];            // fc = F + Q @ T

// ---------------------------------------------------------------------------
// helpers
// ---------------------------------------------------------------------------
__device__ __forceinline__ float tf32_rna(float x) {
    uint32_t r;
    asm("cvt.rna.tf32.f32 %0, %1;" : "=r"(r) : "f"(x));
    return __uint_as_float(r);
}
__device__ __forceinline__ uint32_t f2u(float f) { return __float_as_uint(f); }

__device__ __forceinline__ void mma_tf32(float (&d)[4],
    uint32_t a0, uint32_t a1, uint32_t a2, uint32_t a3,
    uint32_t b0, uint32_t b1)
{
    asm volatile(
        "mma.sync.aligned.m16n8k8.row.col.f32.tf32.tf32.f32 "
        "{%0,%1,%2,%3},{%4,%5,%6,%7},{%8,%9},{%0,%1,%2,%3};"
        : "+f"(d[0]), "+f"(d[1]), "+f"(d[2]), "+f"(d[3])
        : "r"(a0), "r"(a1), "r"(a2), "r"(a3), "r"(b0), "r"(b1));
}

__device__ __forceinline__ void mma_bf16(float (&d)[4],
    const uint32_t (&a)[4], const uint32_t (&b)[2])
{
    asm volatile(
        "mma.sync.aligned.m16n8k16.row.col.f32.bf16.bf16.f32 "
        "{%0,%1,%2,%3},{%4,%5,%6,%7},{%8,%9},{%0,%1,%2,%3};"
        : "+f"(d[0]), "+f"(d[1]), "+f"(d[2]), "+f"(d[3])
        : "r"(a[0]), "r"(a[1]), "r"(a[2]), "r"(a[3]), "r"(b[0]), "r"(b[1]));
}

// ===========================================================================
// bf16 tensor GEMM, ABT form: C[M,N] = A[M,K] * B[N,K]^T (fp32 in/out)
// splitcol: block-col index that gets 3-product hi/lo split (~fp32 accuracy);
//           pass negative to split ALL block-cols; other cols = single bf16.
// BM=128, BN=64, BK=32. 256 threads = 8 warps (2m x 4n), warp tile 64x16.
// Smem rows padded to 20 uint32 (80B) -> conflict-free fragment reads.
// ===========================================================================
__global__ void __launch_bounds__(256)
tbgemm_abt(const float* __restrict__ Ag, int lda,
           const float* __restrict__ Bg, int ldb,
           float* __restrict__ Cg, int ldc, int K, int splitcol)
{
    constexpr int SP = 20;  // uint32 per smem row (16 k-pairs + 4 pad)
    __shared__ uint32_t Ah[128*SP], Al[128*SP];
    __shared__ uint32_t Bh[64*SP],  Bl[64*SP];

    const bool dosplit = (splitcol < 0) || ((int)blockIdx.x == splitcol);

    const int m0 = blockIdx.y * 128, n0 = blockIdx.x * 64;
    const int tid = threadIdx.x, lane = tid & 31, wid = tid >> 5;
    const int wm0 = (wid & 1) * 64, wn0 = (wid >> 1) * 16;
    const int r4 = lane >> 2, c4 = lane & 3;

    float acc[4][2][4] = {};

    for (int k0 = 0; k0 < K; k0 += 32) {
        // ---- A tile 128x32 fp32 -> hi (and lo if split) bf16 pairs ----
        #pragma unroll
        for (int e = 0; e < 4; e++) {
            int idx = tid + e * 256;          // 1024 float4 slots
            int row = idx >> 3, fq = idx & 7; // 8 float4 per row
            float4 v = *(const float4*)(Ag + (long)(m0 + row) * lda + k0 + fq * 4);
            __nv_bfloat162 h0 = __floats2bfloat162_rn(v.x, v.y);
            __nv_bfloat162 h1 = __floats2bfloat162_rn(v.z, v.w);
            int o = row * SP + fq * 2;
            *reinterpret_cast<__nv_bfloat162*>(&Ah[o])     = h0;
            *reinterpret_cast<__nv_bfloat162*>(&Ah[o + 1]) = h1;
            if (dosplit) {
                __nv_bfloat162 l0 = __floats2bfloat162_rn(v.x - __bfloat162float(h0.x),
                                                          v.y - __bfloat162float(h0.y));
                __nv_bfloat162 l1 = __floats2bfloat162_rn(v.z - __bfloat162float(h1.x),
                                                          v.w - __bfloat162float(h1.y));
                *reinterpret_cast<__nv_bfloat162*>(&Al[o])     = l0;
                *reinterpret_cast<__nv_bfloat162*>(&Al[o + 1]) = l1;
            }
        }
        // ---- B tile 64x32 fp32 -> hi (and lo if split) bf16 pairs ----
        #pragma unroll
        for (int e = 0; e < 2; e++) {
            int idx = tid + e * 256;          // 512 float4 slots
            int row = idx >> 3, fq = idx & 7;
            float4 v = *(const float4*)(Bg + (long)(n0 + row) * ldb + k0 + fq * 4);
            __nv_bfloat162 h0 = __floats2bfloat162_rn(v.x, v.y);
            __nv_bfloat162 h1 = __floats2bfloat162_rn(v.z, v.w);
            int o = row * SP + fq * 2;
            *reinterpret_cast<__nv_bfloat162*>(&Bh[o])     = h0;
            *reinterpret_cast<__nv_bfloat162*>(&Bh[o + 1]) = h1;
            if (dosplit) {
                __nv_bfloat162 l0 = __floats2bfloat162_rn(v.x - __bfloat162float(h0.x),
                                                          v.y - __bfloat162float(h0.y));
                __nv_bfloat162 l1 = __floats2bfloat162_rn(v.z - __bfloat162float(h1.x),
                                                          v.w - __bfloat162float(h1.y));
                *reinterpret_cast<__nv_bfloat162*>(&Bl[o])     = l0;
                *reinterpret_cast<__nv_bfloat162*>(&Bl[o + 1]) = l1;
            }
        }
        __syncthreads();

        #pragma unroll
        for (int kp = 0; kp < 16; kp += 8) {   // two k16 steps per BK=32
            uint32_t ah[4][4], bh[2][2];
            #pragma unroll
            for (int mt = 0; mt < 4; mt++) {
                int r = (wm0 + mt * 16 + r4) * SP + kp + c4;
                ah[mt][0] = Ah[r];          ah[mt][1] = Ah[r + 8*SP];
                ah[mt][2] = Ah[r + 4];      ah[mt][3] = Ah[r + 8*SP + 4];
            }
            #pragma unroll
            for (int nt = 0; nt < 2; nt++) {
                int r = (wn0 + nt * 8 + r4) * SP + kp + c4;
                bh[nt][0] = Bh[r];  bh[nt][1] = Bh[r + 4];
            }
            #pragma unroll
            for (int mt = 0; mt < 4; mt++)
                #pragma unroll
                for (int nt = 0; nt < 2; nt++)
                    mma_bf16(acc[mt][nt], ah[mt], bh[nt]);      // hi*hi

            if (dosplit) {
                uint32_t al[4][4], bl[2][2];
                #pragma unroll
                for (int mt = 0; mt < 4; mt++) {
                    int r = (wm0 + mt * 16 + r4) * SP + kp + c4;
                    al[mt][0] = Al[r];          al[mt][1] = Al[r + 8*SP];
                    al[mt][2] = Al[r + 4];      al[mt][3] = Al[r + 8*SP + 4];
                }
                #pragma unroll
                for (int nt = 0; nt < 2; nt++) {
                    int r = (wn0 + nt * 8 + r4) * SP + kp + c4;
                    bl[nt][0] = Bl[r];  bl[nt][1] = Bl[r + 4];
                }
                #pragma unroll
                for (int mt = 0; mt < 4; mt++)
                    #pragma unroll
                    for (int nt = 0; nt < 2; nt++) {
                        mma_bf16(acc[mt][nt], ah[mt], bl[nt]);  // hi*lo
                        mma_bf16(acc[mt][nt], al[mt], bh[nt]);  // lo*hi
                    }
            }
        }
        __syncthreads();
    }

    #pragma unroll
    for (int mt = 0; mt < 4; mt++)
        #pragma unroll
        for (int nt = 0; nt < 2; nt++) {
            int row = m0 + wm0 + mt * 16 + r4;
            int col = n0 + wn0 + nt * 8 + 2 * c4;
            *(float2*)(Cg + (long)row * ldc + col) =
                make_float2(acc[mt][nt][0], acc[mt][nt][1]);
            *(float2*)(Cg + (long)(row + 8) * ldc + col) =
                make_float2(acc[mt][nt][2], acc[mt][nt][3]);
        }
}

// ===========================================================================
// Tensor GEMM (tf32), ATB form: C[64,N] = A[L,64]^T * B[L,N] over rows L.
// grid: (N/64, NSPLIT, batch).
// ===========================================================================
__global__ void __launch_bounds__(256)
tgemm_atb(const float* __restrict__ Ag, int lda, long sAb,
          const float* __restrict__ Bg, int ldb, long sBb,
          float* __restrict__ Cg, long sCb, long sCsplit, int ldc,
          int Lchunk)
{
    constexpr int BK = 16, LDT = 64 + 4;
    __shared__ float As[BK][LDT];
    __shared__ float Bs[BK][LDT];

    const int b = blockIdx.z, sp = blockIdx.y;
    const long l0b = (long)sp * Lchunk;
    Ag += (long)b * sAb;  Bg += (long)b * sBb;
    Cg += (long)b * sCb + (long)sp * sCsplit;
    const int n0 = blockIdx.x * 64;
    const int tid = threadIdx.x, lane = tid & 31, wid = tid >> 5;
    const int wm0 = (wid & 1) * 32, wn0 = (wid >> 1) * 16;
    const int r4 = lane >> 2, c4 = lane & 3;
    const int lrow = tid >> 4, lc4 = (tid & 15) * 4;

    float acc[2][2][4] = {};

    for (int l0 = 0; l0 < Lchunk; l0 += BK) {
        {
            float4 v = *(const float4*)(Ag + (l0b + l0 + lrow) * lda + lc4);
            As[lrow][lc4+0] = tf32_rna(v.x);  As[lrow][lc4+1] = tf32_rna(v.y);
            As[lrow][lc4+2] = tf32_rna(v.z);  As[lrow][lc4+3] = tf32_rna(v.w);
            float4 w = *(const float4*)(Bg + (l0b + l0 + lrow) * ldb + n0 + lc4);
            Bs[lrow][lc4+0] = tf32_rna(w.x);  Bs[lrow][lc4+1] = tf32_rna(w.y);
            Bs[lrow][lc4+2] = tf32_rna(w.z);  Bs[lrow][lc4+3] = tf32_rna(w.w);
        }
        __syncthreads();
        #pragma unroll
        for (int kk = 0; kk < BK; kk += 8) {
            uint32_t af[2][4], bf[2][2];
            #pragma unroll
            for (int mt = 0; mt < 2; mt++) {
                int row = wm0 + mt*16 + r4;
                af[mt][0] = f2u(As[kk + c4    ][row    ]);
                af[mt][1] = f2u(As[kk + c4    ][row + 8]);
                af[mt][2] = f2u(As[kk + c4 + 4][row    ]);
                af[mt][3] = f2u(As[kk + c4 + 4][row + 8]);
            }
            #pragma unroll
            for (int nt = 0; nt < 2; nt++) {
                int col = wn0 + nt*8 + r4;
                bf[nt][0] = f2u(Bs[kk + c4    ][col]);
                bf[nt][1] = f2u(Bs[kk + c4 + 4][col]);
            }
            #pragma unroll
            for (int mt = 0; mt < 2; mt++)
                #pragma unroll
                for (int nt = 0; nt < 2; nt++)
                    mma_tf32(acc[mt][nt], af[mt][0], af[mt][1], af[mt][2], af[mt][3],
                             bf[nt][0], bf[nt][1]);
        }
        __syncthreads();
    }
    #pragma unroll
    for (int mt = 0; mt < 2; mt++)
        #pragma unroll
        for (int nt = 0; nt < 2; nt++) {
            int row = wm0 + mt*16 + r4;
            int col = n0 + wn0 + nt*8 + 2*c4;
            *(float2*)(Cg + (long)row * ldc + col) =
                make_float2(acc[mt][nt][0], acc[mt][nt][1]);
            *(float2*)(Cg + (long)(row + 8) * ldc + col) =
                make_float2(acc[mt][nt][2], acc[mt][nt][3]);
        }
}

// ===========================================================================
// SIMT fp32 NN GEMM (U2 only): C[M,N] = A[M,K]*B[K,N], split-K via z
// ===========================================================================
template<int BM,int BN,int BK,int TM,int TN>
__global__ void __launch_bounds__((BM/TM)*(BN/TN))
gemm_nn(const float* __restrict__ A, long sA, int lda,
        const float* __restrict__ B, long sB, int ldb,
        float* __restrict__ C, long sC, int ldc,
        int K)
{
    constexpr int THREADS = (BM/TM)*(BN/TN);
    __shared__ float As[BK][BM];
    __shared__ float Bs[BK][BN];

    const int bz = blockIdx.z;
    A += bz * sA;  B += bz * sB;  C += bz * sC;

    const int m0 = blockIdx.y * BM;
    const int n0 = blockIdx.x * BN;
    const int tid = threadIdx.x;
    const int tx = tid % (BN/TN);
    const int ty = tid / (BN/TN);

    float acc[TM][TN];
    #pragma unroll
    for (int i = 0; i < TM; i++)
        #pragma unroll
        for (int j = 0; j < TN; j++) acc[i][j] = 0.f;

    for (int k0 = 0; k0 < K; k0 += BK) {
        #pragma unroll
        for (int e = 0; e < (BM*BK/4)/THREADS; e++) {
            int idx = tid + e*THREADS;
            int row = idx / (BK/4), cv = idx % (BK/4);
            float4 v = *(const float4*)(A + (long)(m0+row)*lda + k0 + cv*4);
            As[cv*4+0][row] = v.x;  As[cv*4+1][row] = v.y;
            As[cv*4+2][row] = v.z;  As[cv*4+3][row] = v.w;
        }
        #pragma unroll
        for (int e = 0; e < (BK*BN/4)/THREADS; e++) {
            int idx = tid + e*THREADS;
            int row = idx / (BN/4), cv = idx % (BN/4);
            *(float4*)&Bs[row][cv*4] =
                *(const float4*)(B + (long)(k0+row)*ldb + n0 + cv*4);
        }
        __syncthreads();
        #pragma unroll
        for (int k = 0; k < BK; k++) {
            float a[TM], b[TN];
            #pragma unroll
            for (int i = 0; i < TM; i += 4) *(float4*)(a+i) = *(const float4*)&As[k][ty*TM+i];
            #pragma unroll
            for (int j = 0; j < TN; j += 4) *(float4*)(b+j) = *(const float4*)&Bs[k][tx*TN+j];
            #pragma unroll
            for (int i = 0; i < TM; i++)
                #pragma unroll
                for (int j = 0; j < TN; j++) acc[i][j] += a[i]*b[j];
        }
        __syncthreads();
    }
    #pragma unroll
    for (int i = 0; i < TM; i++) {
        int row = m0 + ty*TM + i;
        #pragma unroll
        for (int j = 0; j < TN; j += 4) {
            float4 v;
            v.x = acc[i][j];   v.y = acc[i][j+1];
            v.z = acc[i][j+2]; v.w = acc[i][j+3];
            *(float4*)(C + (long)row*ldc + n0 + tx*TN + j) = v;
        }
    }
}

// Sum S split partials
template<int S>
__global__ void reduceN(const float* __restrict__ p, float* __restrict__ o, int n)
{
    int i = blockIdx.x * 256 + threadIdx.x;
    if (i < n) {
        float s = 0.f;
        #pragma unroll
        for (int j = 0; j < S; j++) s += p[i + (long)j * n];
        o[i] = s;
    }
}

// ===========================================================================
// fc = F + Q @ T_b : per block 64 rows (one batch), fp32 exact.
// qkfp row: Q at +0, F at +128. Output fc [MTOT x 64] fp32.
// ===========================================================================
__global__ void __launch_bounds__(256)
fc_kernel(const float* __restrict__ qkfp, const float* __restrict__ T,
          float* __restrict__ fc)
{
    __shared__ float Qs[64][68];
    __shared__ float Ts[64][68];

    const int r0 = blockIdx.x * 64;       // 64 rows, same batch (2048 % 64 == 0)
    const int b  = r0 / NSEQ;
    const int tid = threadIdx.x;

    #pragma unroll
    for (int e = 0; e < 4; e++) {
        int idx = tid + e * 256;          // 1024 float4 slots
        int row = idx >> 4, fq = idx & 15;
        float4 q = *(const float4*)(qkfp + (long)(r0 + row) * 256 + fq * 4);
        *(float4*)&Qs[row][fq * 4] = q;
        float4 t = *(const float4*)(T + (long)b * 4096 + row * 64 + fq * 4);
        *(float4*)&Ts[row][fq * 4] = t;
    }
    __syncthreads();

    const int row = tid >> 2;
    const int col0 = (tid & 3) * 16;
    float acc[16];
    #pragma unroll
    for (int j = 0; j < 16; j += 4) {
        float4 f = *(const float4*)(qkfp + (long)(r0 + row) * 256 + 128 + col0 + j);
        acc[j] = f.x; acc[j+1] = f.y; acc[j+2] = f.z; acc[j+3] = f.w;
    }
    #pragma unroll 8
    for (int k = 0; k < 64; k++) {
        float q = Qs[row][k];
        #pragma unroll
        for (int j = 0; j < 16; j += 4) {
            float4 t = *(const float4*)&Ts[k][col0 + j];
            acc[j]   += q * t.x;  acc[j+1] += q * t.y;
            acc[j+2] += q * t.z;  acc[j+3] += q * t.w;
        }
    }
    #pragma unroll
    for (int j = 0; j < 16; j += 4) {
        float4 v; v.x = acc[j]; v.y = acc[j+1]; v.z = acc[j+2]; v.w = acc[j+3];
        *(float4*)(fc + (long)(r0 + row) * 64 + col0 + j) = v;
    }
}

// ============================================================================
extern "C" void kernel_launch(void* const* d_in, const int* in_sizes, int n_in,
                              void* d_out, int out_size)
{
    const float* x  = (const float*)d_in[0];   // [8,2048,1024]
    const float* Wq = (const float*)d_in[1];   // [64,1024]
    const float* Wk = (const float*)d_in[2];   // [64,1024]
    const float* Wv = (const float*)d_in[3];   // [1024,1024]
    const float* W1 = (const float*)d_in[4];   // [64,1024]
    const float* W2 = (const float*)d_in[5];   // [1024,64]
    float* out = (float*)d_out;                // [8,2048,1024]

    float *wext, *qkfp, *u2p, *tpart, *gt, *gfc;
    cudaGetSymbolAddress((void**)&wext,  g_Wext);
    cudaGetSymbolAddress((void**)&qkfp,  g_QKFP);
    cudaGetSymbolAddress((void**)&u2p,   g_U2part);
    cudaGetSymbolAddress((void**)&tpart, g_Tpart);
    cudaGetSymbolAddress((void**)&gt,    g_T);
    cudaGetSymbolAddress((void**)&gfc,   g_fc);

    // Stack [Wq; Wk; W1] -> g_Wext rows 0..191
    cudaMemcpyAsync(wext,            Wq, (size_t)DKK*DD*sizeof(float), cudaMemcpyDeviceToDevice);
    cudaMemcpyAsync(wext + DKK*DD,   Wk, (size_t)DKK*DD*sizeof(float), cudaMemcpyDeviceToDevice);
    cudaMemcpyAsync(wext + 2*DKK*DD, W1, (size_t)DKK*DD*sizeof(float), cudaMemcpyDeviceToDevice);

    // U2 = W1 @ Wv : [64,1024], 32-way split-K, into g_Wext rows 192..255
    gemm_nn<64,64,16,4,4><<<dim3(16,1,32), 256>>>(
        W1, 32, DD,  Wv, (long)32*DD, DD,  u2p, (long)DKK*DD, DD,  32);
    reduceN<32><<<(DKK*DD + 255)/256, 256>>>(u2p, wext + (long)192*DD, DKK*DD);

    // QKFP = x @ Wext^T : [16384,256]; only block-col 2 (=F) gets the split
    tbgemm_abt<<<dim3(4, 128), 256>>>(x, DD, wext, DD, qkfp, 256, DD, /*splitcol=*/2);

    // T_b = K_b^T P_b : [8,64,64]  (tf32, 32-way L-split) + reduce
    tgemm_atb<<<dim3(1, 32, 8), 256>>>(
        qkfp + 64,  256, (long)NSEQ*256,
        qkfp + 192, 256, (long)NSEQ*256,
        tpart, (long)DKK*DKK, (long)BB*DKK*DKK, DKK,
        NSEQ/32);
    reduceN<32><<<(BB*DKK*DKK + 255)/256, 256>>>(tpart, gt, BB*DKK*DKK);

    // fc = F + Q @ T : [16384,64] fp32
    fc_kernel<<<MTOT/64, 256>>>(qkfp, gt, gfc);

    // out = fc @ W2^T : [16384,1024]  (all columns split — direct path)
    tbgemm_abt<<<dim3(16, 128), 256>>>(gfc, DKK, W2, DKK, out, DD, DKK, /*splitcol=*/-1);
}

// round 5
// speedup vs baseline: 2.8675x; 1.0847x over previous
#include <cuda_runtime.h>
#include <cuda_bf16.h>
#include <cstdint>

// Problem dims (fixed by the dataset)
#define BB 8
#define NSEQ 2048
#define DD 1024
#define DKK 64
#define MTOT (BB*NSEQ)   // 16384

// ---------------- scratch (static __device__ — no allocation) ----------------
__device__ float g_Wext[256*DD];            // [Wq;Wk;W1;U2] stacked, 256x1024
__device__ float g_QKFP[(long)MTOT*256];    // per row: Q[0:64] K[64:128] F[128:192] P[192:256]
__device__ float g_U2part[32*DKK*DD];       // split-K partials of U2
__device__ float g_Tpart[32*BB*DKK*DKK];    // split-L partials of T
__device__ float g_T[BB*DKK*DKK];           // T_b = K_b^T P_b
__device__ float g_fc[MTOT*DKK];            // fc = F + Q @ T

// ---------------------------------------------------------------------------
// helpers
// ---------------------------------------------------------------------------
__device__ __forceinline__ float tf32_rna(float x) {
    uint32_t r;
    asm("cvt.rna.tf32.f32 %0, %1;" : "=r"(r) : "f"(x));
    return __uint_as_float(r);
}
__device__ __forceinline__ uint32_t f2u(float f) { return __float_as_uint(f); }

__device__ __forceinline__ void mma_tf32(float (&d)[4],
    uint32_t a0, uint32_t a1, uint32_t a2, uint32_t a3,
    uint32_t b0, uint32_t b1)
{
    asm volatile(
        "mma.sync.aligned.m16n8k8.row.col.f32.tf32.tf32.f32 "
        "{%0,%1,%2,%3},{%4,%5,%6,%7},{%8,%9},{%0,%1,%2,%3};"
        : "+f"(d[0]), "+f"(d[1]), "+f"(d[2]), "+f"(d[3])
        : "r"(a0), "r"(a1), "r"(a2), "r"(a3), "r"(b0), "r"(b1));
}

__device__ __forceinline__ void mma_bf16(float (&d)[4],
    const uint32_t (&a)[4], const uint32_t (&b)[2])
{
    asm volatile(
        "mma.sync.aligned.m16n8k16.row.col.f32.bf16.bf16.f32 "
        "{%0,%1,%2,%3},{%4,%5,%6,%7},{%8,%9},{%0,%1,%2,%3};"
        : "+f"(d[0]), "+f"(d[1]), "+f"(d[2]), "+f"(d[3])
        : "r"(a[0]), "r"(a[1]), "r"(a[2]), "r"(a[3]), "r"(b[0]), "r"(b[1]));
}

// ===========================================================================
// bf16 tensor GEMM, ABT form: C[M,N] = A[M,K] * B[N,K]^T (fp32 in/out)
// splitcol: block-col index that gets 3-product hi/lo split (~fp32 accuracy);
//           negative => split ALL block-cols; other cols = single bf16.
// BM=128, BN=64, BK=32. 256 threads = 8 warps (2m x 4n), warp tile 64x16.
// Software-pipelined: next global tile prefetched into registers while the
// current smem tile feeds the MMAs; convert+store after the post-MMA sync.
// Smem rows padded to 20 uint32 (80B) -> conflict-free fragment reads.
// ===========================================================================
__global__ void __launch_bounds__(256)
tbgemm_abt(const float* __restrict__ Ag, int lda,
           const float* __restrict__ Bg, int ldb,
           float* __restrict__ Cg, int ldc, int K, int splitcol)
{
    constexpr int SP = 20;  // uint32 per smem row (16 k-pairs + 4 pad)
    __shared__ uint32_t Ah[128*SP], Al[128*SP];
    __shared__ uint32_t Bh[64*SP],  Bl[64*SP];

    const bool dosplit = (splitcol < 0) || ((int)blockIdx.x == splitcol);

    const int m0 = blockIdx.y * 128, n0 = blockIdx.x * 64;
    const int tid = threadIdx.x, lane = tid & 31, wid = tid >> 5;
    const int wm0 = (wid & 1) * 64, wn0 = (wid >> 1) * 16;
    const int r4 = lane >> 2, c4 = lane & 3;

    // per-thread fixed load coordinates
    const int lrow = tid >> 3;            // 0..31 (A: +0/+32/+64/+96; B: +0/+32)
    const int lfq  = (tid & 7) * 4;       // float4 column offset (0..28)
    const int so   = lrow * SP + (lfq >> 1);

    float4 va[4], vb[2];

    auto ldg_tiles = [&](int k0) {
        #pragma unroll
        for (int e = 0; e < 4; e++)
            va[e] = *(const float4*)(Ag + (long)(m0 + lrow + e*32) * lda + k0 + lfq);
        #pragma unroll
        for (int e = 0; e < 2; e++)
            vb[e] = *(const float4*)(Bg + (long)(n0 + lrow + e*32) * ldb + k0 + lfq);
    };

    auto cvt_store = [&]() {
        #pragma unroll
        for (int e = 0; e < 4; e++) {
            float4 v = va[e];
            __nv_bfloat162 h0 = __floats2bfloat162_rn(v.x, v.y);
            __nv_bfloat162 h1 = __floats2bfloat162_rn(v.z, v.w);
            int o = so + e*32*SP;
            *reinterpret_cast<__nv_bfloat162*>(&Ah[o])     = h0;
            *reinterpret_cast<__nv_bfloat162*>(&Ah[o + 1]) = h1;
            if (dosplit) {
                __nv_bfloat162 l0 = __floats2bfloat162_rn(v.x - __bfloat162float(h0.x),
                                                          v.y - __bfloat162float(h0.y));
                __nv_bfloat162 l1 = __floats2bfloat162_rn(v.z - __bfloat162float(h1.x),
                                                          v.w - __bfloat162float(h1.y));
                *reinterpret_cast<__nv_bfloat162*>(&Al[o])     = l0;
                *reinterpret_cast<__nv_bfloat162*>(&Al[o + 1]) = l1;
            }
        }
        #pragma unroll
        for (int e = 0; e < 2; e++) {
            float4 v = vb[e];
            __nv_bfloat162 h0 = __floats2bfloat162_rn(v.x, v.y);
            __nv_bfloat162 h1 = __floats2bfloat162_rn(v.z, v.w);
            int o = so + e*32*SP;
            *reinterpret_cast<__nv_bfloat162*>(&Bh[o])     = h0;
            *reinterpret_cast<__nv_bfloat162*>(&Bh[o + 1]) = h1;
            if (dosplit) {
                __nv_bfloat162 l0 = __floats2bfloat162_rn(v.x - __bfloat162float(h0.x),
                                                          v.y - __bfloat162float(h0.y));
                __nv_bfloat162 l1 = __floats2bfloat162_rn(v.z - __bfloat162float(h1.x),
                                                          v.w - __bfloat162float(h1.y));
                *reinterpret_cast<__nv_bfloat162*>(&Bl[o])     = l0;
                *reinterpret_cast<__nv_bfloat162*>(&Bl[o + 1]) = l1;
            }
        }
    };

    float acc[4][2][4] = {};

    // prologue
    ldg_tiles(0);
    cvt_store();
    __syncthreads();

    for (int k0 = 0; k0 < K; k0 += 32) {
        const bool more = (k0 + 32) < K;
        if (more) ldg_tiles(k0 + 32);   // prefetch overlaps the MMAs below

        #pragma unroll
        for (int kp = 0; kp < 16; kp += 8) {   // two k16 steps per BK=32
            uint32_t ah[4][4], bh[2][2];
            #pragma unroll
            for (int mt = 0; mt < 4; mt++) {
                int r = (wm0 + mt * 16 + r4) * SP + kp + c4;
                ah[mt][0] = Ah[r];          ah[mt][1] = Ah[r + 8*SP];
                ah[mt][2] = Ah[r + 4];      ah[mt][3] = Ah[r + 8*SP + 4];
            }
            #pragma unroll
            for (int nt = 0; nt < 2; nt++) {
                int r = (wn0 + nt * 8 + r4) * SP + kp + c4;
                bh[nt][0] = Bh[r];  bh[nt][1] = Bh[r + 4];
            }
            #pragma unroll
            for (int mt = 0; mt < 4; mt++)
                #pragma unroll
                for (int nt = 0; nt < 2; nt++)
                    mma_bf16(acc[mt][nt], ah[mt], bh[nt]);      // hi*hi

            if (dosplit) {
                uint32_t al[4][4], bl[2][2];
                #pragma unroll
                for (int mt = 0; mt < 4; mt++) {
                    int r = (wm0 + mt * 16 + r4) * SP + kp + c4;
                    al[mt][0] = Al[r];          al[mt][1] = Al[r + 8*SP];
                    al[mt][2] = Al[r + 4];      al[mt][3] = Al[r + 8*SP + 4];
                }
                #pragma unroll
                for (int nt = 0; nt < 2; nt++) {
                    int r = (wn0 + nt * 8 + r4) * SP + kp + c4;
                    bl[nt][0] = Bl[r];  bl[nt][1] = Bl[r + 4];
                }
                #pragma unroll
                for (int mt = 0; mt < 4; mt++)
                    #pragma unroll
                    for (int nt = 0; nt < 2; nt++) {
                        mma_bf16(acc[mt][nt], ah[mt], bl[nt]);  // hi*lo
                        mma_bf16(acc[mt][nt], al[mt], bh[nt]);  // lo*hi
                    }
            }
        }
        __syncthreads();
        if (more) {
            cvt_store();
            __syncthreads();
        }
    }

    #pragma unroll
    for (int mt = 0; mt < 4; mt++)
        #pragma unroll
        for (int nt = 0; nt < 2; nt++) {
            int row = m0 + wm0 + mt * 16 + r4;
            int col = n0 + wn0 + nt * 8 + 2 * c4;
            *(float2*)(Cg + (long)row * ldc + col) =
                make_float2(acc[mt][nt][0], acc[mt][nt][1]);
            *(float2*)(Cg + (long)(row + 8) * ldc + col) =
                make_float2(acc[mt][nt][2], acc[mt][nt][3]);
        }
}

// ===========================================================================
// Tensor GEMM (tf32), ATB form: C[64,N] = A[L,64]^T * B[L,N] over rows L.
// grid: (N/64, NSPLIT, batch).
// ===========================================================================
__global__ void __launch_bounds__(256)
tgemm_atb(const float* __restrict__ Ag, int lda, long sAb,
          const float* __restrict__ Bg, int ldb, long sBb,
          float* __restrict__ Cg, long sCb, long sCsplit, int ldc,
          int Lchunk)
{
    constexpr int BK = 16, LDT = 64 + 4;
    __shared__ float As[BK][LDT];
    __shared__ float Bs[BK][LDT];

    const int b = blockIdx.z, sp = blockIdx.y;
    const long l0b = (long)sp * Lchunk;
    Ag += (long)b * sAb;  Bg += (long)b * sBb;
    Cg += (long)b * sCb + (long)sp * sCsplit;
    const int n0 = blockIdx.x * 64;
    const int tid = threadIdx.x, lane = tid & 31, wid = tid >> 5;
    const int wm0 = (wid & 1) * 32, wn0 = (wid >> 1) * 16;
    const int r4 = lane >> 2, c4 = lane & 3;
    const int lrow = tid >> 4, lc4 = (tid & 15) * 4;

    float acc[2][2][4] = {};
    float4 va, vb;

    auto ldg = [&](int l0) {
        va = *(const float4*)(Ag + (l0b + l0 + lrow) * lda + lc4);
        vb = *(const float4*)(Bg + (l0b + l0 + lrow) * ldb + n0 + lc4);
    };
    auto store = [&]() {
        As[lrow][lc4+0] = tf32_rna(va.x);  As[lrow][lc4+1] = tf32_rna(va.y);
        As[lrow][lc4+2] = tf32_rna(va.z);  As[lrow][lc4+3] = tf32_rna(va.w);
        Bs[lrow][lc4+0] = tf32_rna(vb.x);  Bs[lrow][lc4+1] = tf32_rna(vb.y);
        Bs[lrow][lc4+2] = tf32_rna(vb.z);  Bs[lrow][lc4+3] = tf32_rna(vb.w);
    };

    ldg(0);
    store();
    __syncthreads();

    for (int l0 = 0; l0 < Lchunk; l0 += BK) {
        const bool more = (l0 + BK) < Lchunk;
        if (more) ldg(l0 + BK);

        #pragma unroll
        for (int kk = 0; kk < BK; kk += 8) {
            uint32_t af[2][4], bf[2][2];
            #pragma unroll
            for (int mt = 0; mt < 2; mt++) {
                int row = wm0 + mt*16 + r4;
                af[mt][0] = f2u(As[kk + c4    ][row    ]);
                af[mt][1] = f2u(As[kk + c4    ][row + 8]);
                af[mt][2] = f2u(As[kk + c4 + 4][row    ]);
                af[mt][3] = f2u(As[kk + c4 + 4][row + 8]);
            }
            #pragma unroll
            for (int nt = 0; nt < 2; nt++) {
                int col = wn0 + nt*8 + r4;
                bf[nt][0] = f2u(Bs[kk + c4    ][col]);
                bf[nt][1] = f2u(Bs[kk + c4 + 4][col]);
            }
            #pragma unroll
            for (int mt = 0; mt < 2; mt++)
                #pragma unroll
                for (int nt = 0; nt < 2; nt++)
                    mma_tf32(acc[mt][nt], af[mt][0], af[mt][1], af[mt][2], af[mt][3],
                             bf[nt][0], bf[nt][1]);
        }
        __syncthreads();
        if (more) {
            store();
            __syncthreads();
        }
    }
    #pragma unroll
    for (int mt = 0; mt < 2; mt++)
        #pragma unroll
        for (int nt = 0; nt < 2; nt++) {
            int row = wm0 + mt*16 + r4;
            int col = n0 + wn0 + nt*8 + 2*c4;
            *(float2*)(Cg + (long)row * ldc + col) =
                make_float2(acc[mt][nt][0], acc[mt][nt][1]);
            *(float2*)(Cg + (long)(row + 8) * ldc + col) =
                make_float2(acc[mt][nt][2], acc[mt][nt][3]);
        }
}

// ===========================================================================
// SIMT fp32 NN GEMM (U2 only): C[M,N] = A[M,K]*B[K,N], split-K via z
// ===========================================================================
template<int BM,int BN,int BK,int TM,int TN>
__global__ void __launch_bounds__((BM/TM)*(BN/TN))
gemm_nn(const float* __restrict__ A, long sA, int lda,
        const float* __restrict__ B, long sB, int ldb,
        float* __restrict__ C, long sC, int ldc,
        int K)
{
    constexpr int THREADS = (BM/TM)*(BN/TN);
    __shared__ float As[BK][BM];
    __shared__ float Bs[BK][BN];

    const int bz = blockIdx.z;
    A += bz * sA;  B += bz * sB;  C += bz * sC;

    const int m0 = blockIdx.y * BM;
    const int n0 = blockIdx.x * BN;
    const int tid = threadIdx.x;
    const int tx = tid % (BN/TN);
    const int ty = tid / (BN/TN);

    float acc[TM][TN];
    #pragma unroll
    for (int i = 0; i < TM; i++)
        #pragma unroll
        for (int j = 0; j < TN; j++) acc[i][j] = 0.f;

    for (int k0 = 0; k0 < K; k0 += BK) {
        #pragma unroll
        for (int e = 0; e < (BM*BK/4)/THREADS; e++) {
            int idx = tid + e*THREADS;
            int row = idx / (BK/4), cv = idx % (BK/4);
            float4 v = *(const float4*)(A + (long)(m0+row)*lda + k0 + cv*4);
            As[cv*4+0][row] = v.x;  As[cv*4+1][row] = v.y;
            As[cv*4+2][row] = v.z;  As[cv*4+3][row] = v.w;
        }
        #pragma unroll
        for (int e = 0; e < (BK*BN/4)/THREADS; e++) {
            int idx = tid + e*THREADS;
            int row = idx / (BN/4), cv = idx % (BN/4);
            *(float4*)&Bs[row][cv*4] =
                *(const float4*)(B + (long)(k0+row)*ldb + n0 + cv*4);
        }
        __syncthreads();
        #pragma unroll
        for (int k = 0; k < BK; k++) {
            float a[TM], b[TN];
            #pragma unroll
            for (int i = 0; i < TM; i += 4) *(float4*)(a+i) = *(const float4*)&As[k][ty*TM+i];
            #pragma unroll
            for (int j = 0; j < TN; j += 4) *(float4*)(b+j) = *(const float4*)&Bs[k][tx*TN+j];
            #pragma unroll
            for (int i = 0; i < TM; i++)
                #pragma unroll
                for (int j = 0; j < TN; j++) acc[i][j] += a[i]*b[j];
        }
        __syncthreads();
    }
    #pragma unroll
    for (int i = 0; i < TM; i++) {
        int row = m0 + ty*TM + i;
        #pragma unroll
        for (int j = 0; j < TN; j += 4) {
            float4 v;
            v.x = acc[i][j];   v.y = acc[i][j+1];
            v.z = acc[i][j+2]; v.w = acc[i][j+3];
            *(float4*)(C + (long)row*ldc + n0 + tx*TN + j) = v;
        }
    }
}

// Sum S split partials
template<int S>
__global__ void reduceN(const float* __restrict__ p, float* __restrict__ o, int n)
{
    int i = blockIdx.x * 256 + threadIdx.x;
    if (i < n) {
        float s = 0.f;
        #pragma unroll
        for (int j = 0; j < S; j++) s += p[i + (long)j * n];
        o[i] = s;
    }
}

// ===========================================================================
// fc = F + Q @ T_b : per block 64 rows (one batch), fp32 exact.
// qkfp row: Q at +0, F at +128. Output fc [MTOT x 64] fp32.
// ===========================================================================
__global__ void __launch_bounds__(256)
fc_kernel(const float* __restrict__ qkfp, const float* __restrict__ T,
          float* __restrict__ fc)
{
    __shared__ float Qs[64][68];
    __shared__ float Ts[64][68];

    const int r0 = blockIdx.x * 64;       // 64 rows, same batch (2048 % 64 == 0)
    const int b  = r0 / NSEQ;
    const int tid = threadIdx.x;

    #pragma unroll
    for (int e = 0; e < 4; e++) {
        int idx = tid + e * 256;          // 1024 float4 slots
        int row = idx >> 4, fq = idx & 15;
        float4 q = *(const float4*)(qkfp + (long)(r0 + row) * 256 + fq * 4);
        *(float4*)&Qs[row][fq * 4] = q;
        float4 t = *(const float4*)(T + (long)b * 4096 + row * 64 + fq * 4);
        *(float4*)&Ts[row][fq * 4] = t;
    }
    __syncthreads();

    const int row = tid >> 2;
    const int col0 = (tid & 3) * 16;
    float acc[16];
    #pragma unroll
    for (int j = 0; j < 16; j += 4) {
        float4 f = *(const float4*)(qkfp + (long)(r0 + row) * 256 + 128 + col0 + j);
        acc[j] = f.x; acc[j+1] = f.y; acc[j+2] = f.z; acc[j+3] = f.w;
    }
    #pragma unroll 8
    for (int k = 0; k < 64; k++) {
        float q = Qs[row][k];
        #pragma unroll
        for (int j = 0; j < 16; j += 4) {
            float4 t = *(const float4*)&Ts[k][col0 + j];
            acc[j]   += q * t.x;  acc[j+1] += q * t.y;
            acc[j+2] += q * t.z;  acc[j+3] += q * t.w;
        }
    }
    #pragma unroll
    for (int j = 0; j < 16; j += 4) {
        float4 v; v.x = acc[j]; v.y = acc[j+1]; v.z = acc[j+2]; v.w = acc[j+3];
        *(float4*)(fc + (long)(r0 + row) * 64 + col0 + j) = v;
    }
}

// ============================================================================
extern "C" void kernel_launch(void* const* d_in, const int* in_sizes, int n_in,
                              void* d_out, int out_size)
{
    const float* x  = (const float*)d_in[0];   // [8,2048,1024]
    const float* Wq = (const float*)d_in[1];   // [64,1024]
    const float* Wk = (const float*)d_in[2];   // [64,1024]
    const float* Wv = (const float*)d_in[3];   // [1024,1024]
    const float* W1 = (const float*)d_in[4];   // [64,1024]
    const float* W2 = (const float*)d_in[5];   // [1024,64]
    float* out = (float*)d_out;                // [8,2048,1024]

    float *wext, *qkfp, *u2p, *tpart, *gt, *gfc;
    cudaGetSymbolAddress((void**)&wext,  g_Wext);
    cudaGetSymbolAddress((void**)&qkfp,  g_QKFP);
    cudaGetSymbolAddress((void**)&u2p,   g_U2part);
    cudaGetSymbolAddress((void**)&tpart, g_Tpart);
    cudaGetSymbolAddress((void**)&gt,    g_T);
    cudaGetSymbolAddress((void**)&gfc,   g_fc);

    // Stack [Wq; Wk; W1] -> g_Wext rows 0..191
    cudaMemcpyAsync(wext,            Wq, (size_t)DKK*DD*sizeof(float), cudaMemcpyDeviceToDevice);
    cudaMemcpyAsync(wext + DKK*DD,   Wk, (size_t)DKK*DD*sizeof(float), cudaMemcpyDeviceToDevice);
    cudaMemcpyAsync(wext + 2*DKK*DD, W1, (size_t)DKK*DD*sizeof(float), cudaMemcpyDeviceToDevice);

    // U2 = W1 @ Wv : [64,1024], 32-way split-K, into g_Wext rows 192..255
    gemm_nn<64,64,16,4,4><<<dim3(16,1,32), 256>>>(
        W1, 32, DD,  Wv, (long)32*DD, DD,  u2p, (long)DKK*DD, DD,  32);
    reduceN<32><<<(DKK*DD + 255)/256, 256>>>(u2p, wext + (long)192*DD, DKK*DD);

    // QKFP = x @ Wext^T : [16384,256]; only block-col 2 (=F) gets the split
    tbgemm_abt<<<dim3(4, 128), 256>>>(x, DD, wext, DD, qkfp, 256, DD, /*splitcol=*/2);

    // T_b = K_b^T P_b : [8,64,64]  (tf32, 32-way L-split) + reduce
    tgemm_atb<<<dim3(1, 32, 8), 256>>>(
        qkfp + 64,  256, (long)NSEQ*256,
        qkfp + 192, 256, (long)NSEQ*256,
        tpart, (long)DKK*DKK, (long)BB*DKK*DKK, DKK,
        NSEQ/32);
    reduceN<32><<<(BB*DKK*DKK + 255)/256, 256>>>(tpart, gt, BB*DKK*DKK);

    // fc = F + Q @ T : [16384,64] fp32
    fc_kernel<<<MTOT/64, 256>>>(qkfp, gt, gfc);

    // out = fc @ W2^T : [16384,1024]  (all columns split — direct path)
    tbgemm_abt<<<dim3(16, 128), 256>>>(gfc, DKK, W2, DKK, out, DD, DKK, /*splitcol=*/-1);
}

// round 6
// speedup vs baseline: 2.9898x; 1.0427x over previous
#include <cuda_runtime.h>
#include <cuda_bf16.h>
#include <cstdint>

// Problem dims (fixed by the dataset)
#define BB 8
#define NSEQ 2048
#define DD 1024
#define DKK 64
#define MTOT (BB*NSEQ)   // 16384

// ---------------- scratch (static __device__ — no allocation) ----------------
__device__ float g_Wext[256*DD];            // [Wq;Wk;W1;U2] stacked, 256x1024
__device__ float g_QKFP[(long)MTOT*256];    // per row: Q[0:64] K[64:128] F[128:192] P[192:256]
__device__ float g_U2part[32*DKK*DD];       // split-K partials of U2
__device__ float g_Tpart[32*BB*DKK*DKK];    // split-L partials of T
__device__ float g_T[BB*DKK*DKK];           // T_b = K_b^T P_b
__device__ float g_fc[MTOT*DKK];            // fc = F + Q @ T

// ---------------------------------------------------------------------------
// helpers
// ---------------------------------------------------------------------------
__device__ __forceinline__ float tf32_rna(float x) {
    uint32_t r;
    asm("cvt.rna.tf32.f32 %0, %1;" : "=r"(r) : "f"(x));
    return __uint_as_float(r);
}
__device__ __forceinline__ uint32_t f2u(float f) { return __float_as_uint(f); }

__device__ __forceinline__ void mma_tf32(float (&d)[4],
    uint32_t a0, uint32_t a1, uint32_t a2, uint32_t a3,
    uint32_t b0, uint32_t b1)
{
    asm volatile(
        "mma.sync.aligned.m16n8k8.row.col.f32.tf32.tf32.f32 "
        "{%0,%1,%2,%3},{%4,%5,%6,%7},{%8,%9},{%0,%1,%2,%3};"
        : "+f"(d[0]), "+f"(d[1]), "+f"(d[2]), "+f"(d[3])
        : "r"(a0), "r"(a1), "r"(a2), "r"(a3), "r"(b0), "r"(b1));
}

__device__ __forceinline__ void mma_bf16(float (&d)[4],
    const uint32_t (&a)[4], const uint32_t (&b)[2])
{
    asm volatile(
        "mma.sync.aligned.m16n8k16.row.col.f32.bf16.bf16.f32 "
        "{%0,%1,%2,%3},{%4,%5,%6,%7},{%8,%9},{%0,%1,%2,%3};"
        : "+f"(d[0]), "+f"(d[1]), "+f"(d[2]), "+f"(d[3])
        : "r"(a[0]), "r"(a[1]), "r"(a[2]), "r"(a[3]), "r"(b[0]), "r"(b[1]));
}

__device__ __forceinline__ void ldmx4(uint32_t (&r)[4], uint32_t addr) {
    asm volatile("ldmatrix.sync.aligned.m8n8.x4.shared.b16 {%0,%1,%2,%3}, [%4];"
        : "=r"(r[0]), "=r"(r[1]), "=r"(r[2]), "=r"(r[3]) : "r"(addr));
}
__device__ __forceinline__ void ldmx2(uint32_t (&r)[2], uint32_t addr) {
    asm volatile("ldmatrix.sync.aligned.m8n8.x2.shared.b16 {%0,%1}, [%2];"
        : "=r"(r[0]), "=r"(r[1]) : "r"(addr));
}

// ===========================================================================
// bf16 tensor GEMM, ABT form: C[M,N] = A[M,K] * B[N,K]^T (fp32 in/out)
// splitcol: block-col index that gets 3-product hi/lo split (~fp32 accuracy);
//           negative => split ALL block-cols; other cols = single bf16.
// BM=128, BN=64, BK=32. 256 threads = 8 warps (2m x 4n), warp tile 64x16.
// Software-pipelined global->reg prefetch; ldmatrix fragment loads.
// Smem rows padded to 20 uint32 (80B): the 8 rows of every 8x8 ldmatrix
// land on banks {0,20,8,28,16,4,24,12}*4B -> all 32 banks, conflict-free.
// ===========================================================================
__global__ void __launch_bounds__(256)
tbgemm_abt(const float* __restrict__ Ag, int lda,
           const float* __restrict__ Bg, int ldb,
           float* __restrict__ Cg, int ldc, int K, int splitcol)
{
    constexpr int SP = 20;  // uint32 per smem row (16 k-pairs + 4 pad)
    __shared__ uint32_t Ah[128*SP], Al[128*SP];
    __shared__ uint32_t Bh[64*SP],  Bl[64*SP];

    const bool dosplit = (splitcol < 0) || ((int)blockIdx.x == splitcol);

    const int m0 = blockIdx.y * 128, n0 = blockIdx.x * 64;
    const int tid = threadIdx.x, lane = tid & 31, wid = tid >> 5;
    const int wm0 = (wid & 1) * 64, wn0 = (wid >> 1) * 16;

    // per-thread fixed global-load coordinates
    const int lrow = tid >> 3;            // 0..31 (A: +0/+32/+64/+96; B: +0/+32)
    const int lfq  = (tid & 7) * 4;       // float4 column offset (0..28)
    const int so   = lrow * SP + (lfq >> 1);

    // ldmatrix per-lane source addresses (loop-invariant)
    // A x4: mat0 [m0-7,k0-7], mat1 [m8-15,k0-7], mat2 [m0-7,k8-15], mat3 [m8-15,k8-15]
    const int arowoff = ((lane >> 3) & 1) * 8 + (lane & 7);
    const int akoff   = (lane >> 4) * 4;            // uint32 units (16B = k8)
    uint32_t a_addr[4];
    #pragma unroll
    for (int mt = 0; mt < 4; mt++)
        a_addr[mt] = (uint32_t)__cvta_generic_to_shared(
            &Ah[(wm0 + mt * 16 + arowoff) * SP + akoff]);
    // B x2: mat0 [n0-7,k0-7], mat1 [n0-7,k8-15]; only lanes 0-15 supply addrs
    const int lb = lane & 15;
    const int browoff = lb & 7;
    const int bkoff   = ((lb >> 3) & 1) * 4;
    uint32_t b_addr[2];
    #pragma unroll
    for (int nt = 0; nt < 2; nt++)
        b_addr[nt] = (uint32_t)__cvta_generic_to_shared(
            &Bh[(wn0 + nt * 8 + browoff) * SP + bkoff]);
    const uint32_t dAl = (uint32_t)((const char*)Al - (const char*)Ah);
    const uint32_t dBl = (uint32_t)((const char*)Bl - (const char*)Bh);

    float4 va[4], vb[2];

    auto ldg_tiles = [&](int k0) {
        #pragma unroll
        for (int e = 0; e < 4; e++)
            va[e] = *(const float4*)(Ag + (long)(m0 + lrow + e*32) * lda + k0 + lfq);
        #pragma unroll
        for (int e = 0; e < 2; e++)
            vb[e] = *(const float4*)(Bg + (long)(n0 + lrow + e*32) * ldb + k0 + lfq);
    };

    auto cvt_store = [&]() {
        #pragma unroll
        for (int e = 0; e < 4; e++) {
            float4 v = va[e];
            __nv_bfloat162 h0 = __floats2bfloat162_rn(v.x, v.y);
            __nv_bfloat162 h1 = __floats2bfloat162_rn(v.z, v.w);
            int o = so + e*32*SP;
            *reinterpret_cast<__nv_bfloat162*>(&Ah[o])     = h0;
            *reinterpret_cast<__nv_bfloat162*>(&Ah[o + 1]) = h1;
            if (dosplit) {
                __nv_bfloat162 l0 = __floats2bfloat162_rn(v.x - __bfloat162float(h0.x),
                                                          v.y - __bfloat162float(h0.y));
                __nv_bfloat162 l1 = __floats2bfloat162_rn(v.z - __bfloat162float(h1.x),
                                                          v.w - __bfloat162float(h1.y));
                *reinterpret_cast<__nv_bfloat162*>(&Al[o])     = l0;
                *reinterpret_cast<__nv_bfloat162*>(&Al[o + 1]) = l1;
            }
        }
        #pragma unroll
        for (int e = 0; e < 2; e++) {
            float4 v = vb[e];
            __nv_bfloat162 h0 = __floats2bfloat162_rn(v.x, v.y);
            __nv_bfloat162 h1 = __floats2bfloat162_rn(v.z, v.w);
            int o = so + e*32*SP;
            *reinterpret_cast<__nv_bfloat162*>(&Bh[o])     = h0;
            *reinterpret_cast<__nv_bfloat162*>(&Bh[o + 1]) = h1;
            if (dosplit) {
                __nv_bfloat162 l0 = __floats2bfloat162_rn(v.x - __bfloat162float(h0.x),
                                                          v.y - __bfloat162float(h0.y));
                __nv_bfloat162 l1 = __floats2bfloat162_rn(v.z - __bfloat162float(h1.x),
                                                          v.w - __bfloat162float(h1.y));
                *reinterpret_cast<__nv_bfloat162*>(&Bl[o])     = l0;
                *reinterpret_cast<__nv_bfloat162*>(&Bl[o + 1]) = l1;
            }
        }
    };

    float acc[4][2][4] = {};

    // prologue
    ldg_tiles(0);
    cvt_store();
    __syncthreads();

    for (int k0 = 0; k0 < K; k0 += 32) {
        const bool more = (k0 + 32) < K;
        if (more) ldg_tiles(k0 + 32);   // prefetch overlaps the MMAs below

        #pragma unroll
        for (int kp = 0; kp < 2; kp++) {       // two k16 steps per BK=32
            const uint32_t kb = kp * 32;       // byte offset (8 uint32)
            uint32_t ah[4][4], bh[2][2];
            #pragma unroll
            for (int mt = 0; mt < 4; mt++) ldmx4(ah[mt], a_addr[mt] + kb);
            #pragma unroll
            for (int nt = 0; nt < 2; nt++) ldmx2(bh[nt], b_addr[nt] + kb);
            #pragma unroll
            for (int mt = 0; mt < 4; mt++)
                #pragma unroll
                for (int nt = 0; nt < 2; nt++)
                    mma_bf16(acc[mt][nt], ah[mt], bh[nt]);      // hi*hi

            if (dosplit) {
                uint32_t al[4][4], bl[2][2];
                #pragma unroll
                for (int mt = 0; mt < 4; mt++) ldmx4(al[mt], a_addr[mt] + dAl + kb);
                #pragma unroll
                for (int nt = 0; nt < 2; nt++) ldmx2(bl[nt], b_addr[nt] + dBl + kb);
                #pragma unroll
                for (int mt = 0; mt < 4; mt++)
                    #pragma unroll
                    for (int nt = 0; nt < 2; nt++) {
                        mma_bf16(acc[mt][nt], ah[mt], bl[nt]);  // hi*lo
                        mma_bf16(acc[mt][nt], al[mt], bh[nt]);  // lo*hi
                    }
            }
        }
        __syncthreads();
        if (more) {
            cvt_store();
            __syncthreads();
        }
    }

    const int r4 = lane >> 2, c4 = lane & 3;
    #pragma unroll
    for (int mt = 0; mt < 4; mt++)
        #pragma unroll
        for (int nt = 0; nt < 2; nt++) {
            int row = m0 + wm0 + mt * 16 + r4;
            int col = n0 + wn0 + nt * 8 + 2 * c4;
            *(float2*)(Cg + (long)row * ldc + col) =
                make_float2(acc[mt][nt][0], acc[mt][nt][1]);
            *(float2*)(Cg + (long)(row + 8) * ldc + col) =
                make_float2(acc[mt][nt][2], acc[mt][nt][3]);
        }
}

// ===========================================================================
// Tensor GEMM (tf32), ATB form: C[64,N] = A[L,64]^T * B[L,N] over rows L.
// grid: (N/64, NSPLIT, batch).
// ===========================================================================
__global__ void __launch_bounds__(256)
tgemm_atb(const float* __restrict__ Ag, int lda, long sAb,
          const float* __restrict__ Bg, int ldb, long sBb,
          float* __restrict__ Cg, long sCb, long sCsplit, int ldc,
          int Lchunk)
{
    constexpr int BK = 16, LDT = 64 + 4;
    __shared__ float As[BK][LDT];
    __shared__ float Bs[BK][LDT];

    const int b = blockIdx.z, sp = blockIdx.y;
    const long l0b = (long)sp * Lchunk;
    Ag += (long)b * sAb;  Bg += (long)b * sBb;
    Cg += (long)b * sCb + (long)sp * sCsplit;
    const int n0 = blockIdx.x * 64;
    const int tid = threadIdx.x, lane = tid & 31, wid = tid >> 5;
    const int wm0 = (wid & 1) * 32, wn0 = (wid >> 1) * 16;
    const int r4 = lane >> 2, c4 = lane & 3;
    const int lrow = tid >> 4, lc4 = (tid & 15) * 4;

    float acc[2][2][4] = {};
    float4 va, vb;

    auto ldg = [&](int l0) {
        va = *(const float4*)(Ag + (l0b + l0 + lrow) * lda + lc4);
        vb = *(const float4*)(Bg + (l0b + l0 + lrow) * ldb + n0 + lc4);
    };
    auto store = [&]() {
        As[lrow][lc4+0] = tf32_rna(va.x);  As[lrow][lc4+1] = tf32_rna(va.y);
        As[lrow][lc4+2] = tf32_rna(va.z);  As[lrow][lc4+3] = tf32_rna(va.w);
        Bs[lrow][lc4+0] = tf32_rna(vb.x);  Bs[lrow][lc4+1] = tf32_rna(vb.y);
        Bs[lrow][lc4+2] = tf32_rna(vb.z);  Bs[lrow][lc4+3] = tf32_rna(vb.w);
    };

    ldg(0);
    store();
    __syncthreads();

    for (int l0 = 0; l0 < Lchunk; l0 += BK) {
        const bool more = (l0 + BK) < Lchunk;
        if (more) ldg(l0 + BK);

        #pragma unroll
        for (int kk = 0; kk < BK; kk += 8) {
            uint32_t af[2][4], bf[2][2];
            #pragma unroll
            for (int mt = 0; mt < 2; mt++) {
                int row = wm0 + mt*16 + r4;
                af[mt][0] = f2u(As[kk + c4    ][row    ]);
                af[mt][1] = f2u(As[kk + c4    ][row + 8]);
                af[mt][2] = f2u(As[kk + c4 + 4][row    ]);
                af[mt][3] = f2u(As[kk + c4 + 4][row + 8]);
            }
            #pragma unroll
            for (int nt = 0; nt < 2; nt++) {
                int col = wn0 + nt*8 + r4;
                bf[nt][0] = f2u(Bs[kk + c4    ][col]);
                bf[nt][1] = f2u(Bs[kk + c4 + 4][col]);
            }
            #pragma unroll
            for (int mt = 0; mt < 2; mt++)
                #pragma unroll
                for (int nt = 0; nt < 2; nt++)
                    mma_tf32(acc[mt][nt], af[mt][0], af[mt][1], af[mt][2], af[mt][3],
                             bf[nt][0], bf[nt][1]);
        }
        __syncthreads();
        if (more) {
            store();
            __syncthreads();
        }
    }
    #pragma unroll
    for (int mt = 0; mt < 2; mt++)
        #pragma unroll
        for (int nt = 0; nt < 2; nt++) {
            int row = wm0 + mt*16 + r4;
            int col = n0 + wn0 + nt*8 + 2*c4;
            *(float2*)(Cg + (long)row * ldc + col) =
                make_float2(acc[mt][nt][0], acc[mt][nt][1]);
            *(float2*)(Cg + (long)(row + 8) * ldc + col) =
                make_float2(acc[mt][nt][2], acc[mt][nt][3]);
        }
}

// ===========================================================================
// SIMT fp32 NN GEMM (U2 only): C[M,N] = A[M,K]*B[K,N], split-K via z
// ===========================================================================
template<int BM,int BN,int BK,int TM,int TN>
__global__ void __launch_bounds__((BM/TM)*(BN/TN))
gemm_nn(const float* __restrict__ A, long sA, int lda,
        const float* __restrict__ B, long sB, int ldb,
        float* __restrict__ C, long sC, int ldc,
        int K)
{
    constexpr int THREADS = (BM/TM)*(BN/TN);
    __shared__ float As[BK][BM];
    __shared__ float Bs[BK][BN];

    const int bz = blockIdx.z;
    A += bz * sA;  B += bz * sB;  C += bz * sC;

    const int m0 = blockIdx.y * BM;
    const int n0 = blockIdx.x * BN;
    const int tid = threadIdx.x;
    const int tx = tid % (BN/TN);
    const int ty = tid / (BN/TN);

    float acc[TM][TN];
    #pragma unroll
    for (int i = 0; i < TM; i++)
        #pragma unroll
        for (int j = 0; j < TN; j++) acc[i][j] = 0.f;

    for (int k0 = 0; k0 < K; k0 += BK) {
        #pragma unroll
        for (int e = 0; e < (BM*BK/4)/THREADS; e++) {
            int idx = tid + e*THREADS;
            int row = idx / (BK/4), cv = idx % (BK/4);
            float4 v = *(const float4*)(A + (long)(m0+row)*lda + k0 + cv*4);
            As[cv*4+0][row] = v.x;  As[cv*4+1][row] = v.y;
            As[cv*4+2][row] = v.z;  As[cv*4+3][row] = v.w;
        }
        #pragma unroll
        for (int e = 0; e < (BK*BN/4)/THREADS; e++) {
            int idx = tid + e*THREADS;
            int row = idx / (BN/4), cv = idx % (BN/4);
            *(float4*)&Bs[row][cv*4] =
                *(const float4*)(B + (long)(k0+row)*ldb + n0 + cv*4);
        }
        __syncthreads();
        #pragma unroll
        for (int k = 0; k < BK; k++) {
            float a[TM], b[TN];
            #pragma unroll
            for (int i = 0; i < TM; i += 4) *(float4*)(a+i) = *(const float4*)&As[k][ty*TM+i];
            #pragma unroll
            for (int j = 0; j < TN; j += 4) *(float4*)(b+j) = *(const float4*)&Bs[k][tx*TN+j];
            #pragma unroll
            for (int i = 0; i < TM; i++)
                #pragma unroll
                for (int j = 0; j < TN; j++) acc[i][j] += a[i]*b[j];
        }
        __syncthreads();
    }
    #pragma unroll
    for (int i = 0; i < TM; i++) {
        int row = m0 + ty*TM + i;
        #pragma unroll
        for (int j = 0; j < TN; j += 4) {
            float4 v;
            v.x = acc[i][j];   v.y = acc[i][j+1];
            v.z = acc[i][j+2]; v.w = acc[i][j+3];
            *(float4*)(C + (long)row*ldc + n0 + tx*TN + j) = v;
        }
    }
}

// Sum S split partials
template<int S>
__global__ void reduceN(const float* __restrict__ p, float* __restrict__ o, int n)
{
    int i = blockIdx.x * 256 + threadIdx.x;
    if (i < n) {
        float s = 0.f;
        #pragma unroll
        for (int j = 0; j < S; j++) s += p[i + (long)j * n];
        o[i] = s;
    }
}

// ===========================================================================
// fc = F + Q @ T_b : per block 64 rows (one batch), fp32 exact.
// qkfp row: Q at +0, F at +128. Output fc [MTOT x 64] fp32.
// ===========================================================================
__global__ void __launch_bounds__(256)
fc_kernel(const float* __restrict__ qkfp, const float* __restrict__ T,
          float* __restrict__ fc)
{
    __shared__ float Qs[64][68];
    __shared__ float Ts[64][68];

    const int r0 = blockIdx.x * 64;       // 64 rows, same batch (2048 % 64 == 0)
    const int b  = r0 / NSEQ;
    const int tid = threadIdx.x;

    #pragma unroll
    for (int e = 0; e < 4; e++) {
        int idx = tid + e * 256;          // 1024 float4 slots
        int row = idx >> 4, fq = idx & 15;
        float4 q = *(const float4*)(qkfp + (long)(r0 + row) * 256 + fq * 4);
        *(float4*)&Qs[row][fq * 4] = q;
        float4 t = *(const float4*)(T + (long)b * 4096 + row * 64 + fq * 4);
        *(float4*)&Ts[row][fq * 4] = t;
    }
    __syncthreads();

    const int row = tid >> 2;
    const int col0 = (tid & 3) * 16;
    float acc[16];
    #pragma unroll
    for (int j = 0; j < 16; j += 4) {
        float4 f = *(const float4*)(qkfp + (long)(r0 + row) * 256 + 128 + col0 + j);
        acc[j] = f.x; acc[j+1] = f.y; acc[j+2] = f.z; acc[j+3] = f.w;
    }
    #pragma unroll 8
    for (int k = 0; k < 64; k++) {
        float q = Qs[row][k];
        #pragma unroll
        for (int j = 0; j < 16; j += 4) {
            float4 t = *(const float4*)&Ts[k][col0 + j];
            acc[j]   += q * t.x;  acc[j+1] += q * t.y;
            acc[j+2] += q * t.z;  acc[j+3] += q * t.w;
        }
    }
    #pragma unroll
    for (int j = 0; j < 16; j += 4) {
        float4 v; v.x = acc[j]; v.y = acc[j+1]; v.z = acc[j+2]; v.w = acc[j+3];
        *(float4*)(fc + (long)(r0 + row) * 64 + col0 + j) = v;
    }
}

// ============================================================================
extern "C" void kernel_launch(void* const* d_in, const int* in_sizes, int n_in,
                              void* d_out, int out_size)
{
    const float* x  = (const float*)d_in[0];   // [8,2048,1024]
    const float* Wq = (const float*)d_in[1];   // [64,1024]
    const float* Wk = (const float*)d_in[2];   // [64,1024]
    const float* Wv = (const float*)d_in[3];   // [1024,1024]
    const float* W1 = (const float*)d_in[4];   // [64,1024]
    const float* W2 = (const float*)d_in[5];   // [1024,64]
    float* out = (float*)d_out;                // [8,2048,1024]

    float *wext, *qkfp, *u2p, *tpart, *gt, *gfc;
    cudaGetSymbolAddress((void**)&wext,  g_Wext);
    cudaGetSymbolAddress((void**)&qkfp,  g_QKFP);
    cudaGetSymbolAddress((void**)&u2p,   g_U2part);
    cudaGetSymbolAddress((void**)&tpart, g_Tpart);
    cudaGetSymbolAddress((void**)&gt,    g_T);
    cudaGetSymbolAddress((void**)&gfc,   g_fc);

    // Stack [Wq; Wk; W1] -> g_Wext rows 0..191
    cudaMemcpyAsync(wext,            Wq, (size_t)DKK*DD*sizeof(float), cudaMemcpyDeviceToDevice);
    cudaMemcpyAsync(wext + DKK*DD,   Wk, (size_t)DKK*DD*sizeof(float), cudaMemcpyDeviceToDevice);
    cudaMemcpyAsync(wext + 2*DKK*DD, W1, (size_t)DKK*DD*sizeof(float), cudaMemcpyDeviceToDevice);

    // U2 = W1 @ Wv : [64,1024], 32-way split-K, into g_Wext rows 192..255
    gemm_nn<64,64,16,4,4><<<dim3(16,1,32), 256>>>(
        W1, 32, DD,  Wv, (long)32*DD, DD,  u2p, (long)DKK*DD, DD,  32);
    reduceN<32><<<(DKK*DD + 255)/256, 256>>>(u2p, wext + (long)192*DD, DKK*DD);

    // QKFP = x @ Wext^T : [16384,256]; only block-col 2 (=F) gets the split
    tbgemm_abt<<<dim3(4, 128), 256>>>(x, DD, wext, DD, qkfp, 256, DD, /*splitcol=*/2);

    // T_b = K_b^T P_b : [8,64,64]  (tf32, 32-way L-split) + reduce
    tgemm_atb<<<dim3(1, 32, 8), 256>>>(
        qkfp + 64,  256, (long)NSEQ*256,
        qkfp + 192, 256, (long)NSEQ*256,
        tpart, (long)DKK*DKK, (long)BB*DKK*DKK, DKK,
        NSEQ/32);
    reduceN<32><<<(BB*DKK*DKK + 255)/256, 256>>>(tpart, gt, BB*DKK*DKK);

    // fc = F + Q @ T : [16384,64] fp32
    fc_kernel<<<MTOT/64, 256>>>(qkfp, gt, gfc);

    // out = fc @ W2^T : [16384,1024]  (all columns split — direct path)
    tbgemm_abt<<<dim3(16, 128), 256>>>(gfc, DKK, W2, DKK, out, DD, DKK, /*splitcol=*/-1);
}